// round 2
// baseline (speedup 1.0000x reference)
#include <cuda_runtime.h>

#define N_NODES 100000
#define N_EDGES 800000
#define H 128
#define HE 256
#define EPS 1e-5f

// ---------------- edge kernel config ----------------
#define TILE_E 64
#define SE 260      // padded stride for h_E tile
#define SMSTR 132   // padded stride for intermediate tiles

// ---------------- node kernel config ----------------
#define NT 32       // nodes per CTA
#define SH 132
#define ST 516

// message accumulator (51.2 MB) — static device global (no allocation allowed)
__device__ float g_dh[(size_t)N_NODES * H];
__device__ int g_idx_is64;

// ---------------------------------------------------------------------------
// Detect whether edge_idx is int64 or int32. If the data is int32, reading it
// as int64 packs two neighbor indices -> values >= 2^32 >> N_NODES.
// ---------------------------------------------------------------------------
__global__ void detect_idx_kernel(const void* eidx) {
    const long long* p = (const long long*)eidx;
    int is64 = 1;
    for (int i = 0; i < 64; i++) {
        long long v = p[i];
        if (v < 0 || v >= N_NODES) { is64 = 0; break; }
    }
    g_idx_is64 = is64;
}

// ---------------------------------------------------------------------------
// GEMM tile helper: acc[4][8] = sA[e0..e0+3][0..K) @ W[K][128] (cols j0..j0+7)
// ---------------------------------------------------------------------------
template <int K, int STRIDEA>
__device__ __forceinline__ void gemm_tile(const float* sA, const float* __restrict__ W,
                                          int e0, int j0, float acc[4][8]) {
#pragma unroll
    for (int i = 0; i < 4; i++)
#pragma unroll
        for (int j = 0; j < 8; j++) acc[i][j] = 0.f;

#pragma unroll 4
    for (int k = 0; k < K; k++) {
        const float4 w0 = *(const float4*)(W + (size_t)k * H + j0);
        const float4 w1 = *(const float4*)(W + (size_t)k * H + j0 + 4);
#pragma unroll
        for (int i = 0; i < 4; i++) {
            float a = sA[(e0 + i) * STRIDEA + k];
            acc[i][0] = fmaf(a, w0.x, acc[i][0]);
            acc[i][1] = fmaf(a, w0.y, acc[i][1]);
            acc[i][2] = fmaf(a, w0.z, acc[i][2]);
            acc[i][3] = fmaf(a, w0.w, acc[i][3]);
            acc[i][4] = fmaf(a, w1.x, acc[i][4]);
            acc[i][5] = fmaf(a, w1.y, acc[i][5]);
            acc[i][6] = fmaf(a, w1.z, acc[i][6]);
            acc[i][7] = fmaf(a, w1.w, acc[i][7]);
        }
    }
}

// ---------------------------------------------------------------------------
// Edge kernel: m = relu(hE@W1+b1); m = relu(m@W2+b2); msg = m@W3+b3;
//              atomicAdd(g_dh[src], msg)
// ---------------------------------------------------------------------------
__global__ __launch_bounds__(256, 1) void edge_kernel(
    const float* __restrict__ hE, const void* __restrict__ eidx,
    const float* __restrict__ W1, const float* __restrict__ b1,
    const float* __restrict__ W2, const float* __restrict__ b2,
    const float* __restrict__ W3, const float* __restrict__ b3) {
    extern __shared__ float smem[];
    float* sE  = smem;                     // TILE_E * SE
    float* sM1 = sE + TILE_E * SE;         // TILE_E * SMSTR
    float* sM2 = sM1 + TILE_E * SMSTR;     // TILE_E * SMSTR

    const int tid = threadIdx.x;
    const long long ebase = (long long)blockIdx.x * TILE_E;
    const int is64 = g_idx_is64;

    // stage h_E tile (64 x 256 f32) into smem, padded rows
    {
        const float4* gE = (const float4*)(hE + ebase * HE);
        for (int i = tid; i < TILE_E * (HE / 4); i += 256) {
            int e = i >> 6, c = i & 63;
            float4 v = gE[(size_t)e * 64 + c];
            float* d = &sE[e * SE + c * 4];
            d[0] = v.x; d[1] = v.y; d[2] = v.z; d[3] = v.w;
        }
    }
    __syncthreads();

    const int colid = tid & 15, rowid = tid >> 4;
    const int j0 = colid * 8, e0 = rowid * 4;

    float acc[4][8];

    // ---- layer 1: K = 256 ----
    gemm_tile<HE, SE>(sE, W1, e0, j0, acc);
    {
        float bb[8];
#pragma unroll
        for (int j = 0; j < 8; j++) bb[j] = b1[j0 + j];
#pragma unroll
        for (int i = 0; i < 4; i++)
#pragma unroll
            for (int j = 0; j < 8; j++) {
                float v = acc[i][j] + bb[j];
                sM1[(e0 + i) * SMSTR + j0 + j] = v > 0.f ? v : 0.f;
            }
    }
    __syncthreads();

    // ---- layer 2: K = 128 ----
    gemm_tile<H, SMSTR>(sM1, W2, e0, j0, acc);
    {
        float bb[8];
#pragma unroll
        for (int j = 0; j < 8; j++) bb[j] = b2[j0 + j];
#pragma unroll
        for (int i = 0; i < 4; i++)
#pragma unroll
            for (int j = 0; j < 8; j++) {
                float v = acc[i][j] + bb[j];
                sM2[(e0 + i) * SMSTR + j0 + j] = v > 0.f ? v : 0.f;
            }
    }
    __syncthreads();

    // ---- layer 3: K = 128, then scatter ----
    gemm_tile<H, SMSTR>(sM2, W3, e0, j0, acc);
    {
        float bb[8];
#pragma unroll
        for (int j = 0; j < 8; j++) bb[j] = b3[j0 + j];
#pragma unroll
        for (int i = 0; i < 4; i++) {
            long long e = ebase + e0 + i;
            long long s = is64 ? ((const long long*)eidx)[e]
                               : (long long)((const int*)eidx)[e];
            float* dst = &g_dh[(size_t)s * H + j0];
#pragma unroll
            for (int j = 0; j < 8; j++) atomicAdd(dst + j, acc[i][j] + bb[j]);
        }
    }
}

// ---------------------------------------------------------------------------
// Node kernel: x = hV + dh/30; h = LN1(x); t = relu(h@D1+db1);
//              dh2 = t@D2+db2; out = LN2(h + dh2)
// ---------------------------------------------------------------------------
__global__ __launch_bounds__(256, 1) void node_kernel(
    const float* __restrict__ hV,
    const float* __restrict__ D1, const float* __restrict__ db1,
    const float* __restrict__ D2, const float* __restrict__ db2,
    const float* __restrict__ g1, const float* __restrict__ be1,
    const float* __restrict__ g2, const float* __restrict__ be2,
    float* __restrict__ out) {
    extern __shared__ float smem[];
    float* sh = smem;             // NT * SH
    float* st = sh + NT * SH;     // NT * ST

    const int tid = threadIdx.x;
    const long long nbase = (long long)blockIdx.x * NT;

    // load x = hV + dh / 30
    {
        const float4* gV = (const float4*)(hV + nbase * H);
        const float4* gD = (const float4*)(g_dh + nbase * H);
        for (int i = tid; i < NT * (H / 4); i += 256) {
            int n = i >> 5, c = i & 31;
            float4 v = gV[(size_t)n * 32 + c];
            float4 d = gD[(size_t)n * 32 + c];
            float* dst = &sh[n * SH + c * 4];
            dst[0] = v.x + d.x / 30.0f;
            dst[1] = v.y + d.y / 30.0f;
            dst[2] = v.z + d.z / 30.0f;
            dst[3] = v.w + d.w / 30.0f;
        }
    }
    __syncthreads();

    // ---- LN1 (two-pass), 8 threads per node, in place ----
    {
        int n = tid >> 3, l = tid & 7;
        float* row = sh + n * SH;
        float s = 0.f;
        for (int c = l; c < H; c += 8) s += row[c];
        s += __shfl_xor_sync(~0u, s, 1);
        s += __shfl_xor_sync(~0u, s, 2);
        s += __shfl_xor_sync(~0u, s, 4);
        float mean = s * (1.f / H);
        float ss = 0.f;
        for (int c = l; c < H; c += 8) { float d = row[c] - mean; ss += d * d; }
        ss += __shfl_xor_sync(~0u, ss, 1);
        ss += __shfl_xor_sync(~0u, ss, 2);
        ss += __shfl_xor_sync(~0u, ss, 4);
        float rstd = rsqrtf(ss * (1.f / H) + EPS);
        for (int c = l; c < H; c += 8)
            row[c] = (row[c] - mean) * rstd * g1[c] + be1[c];
    }
    __syncthreads();

    const int tx = tid & 31, ty = tid >> 5;

    // ---- GEMM1: st[NT][512] = relu(sh @ D1 + db1) ----
    {
        const int n0 = ty * 4, j0 = tx * 16;
        float acc[4][16];
#pragma unroll
        for (int i = 0; i < 4; i++)
#pragma unroll
            for (int j = 0; j < 16; j++) acc[i][j] = 0.f;

#pragma unroll 2
        for (int k = 0; k < H; k++) {
            float4 w0 = *(const float4*)(D1 + (size_t)k * 512 + j0);
            float4 w1 = *(const float4*)(D1 + (size_t)k * 512 + j0 + 4);
            float4 w2 = *(const float4*)(D1 + (size_t)k * 512 + j0 + 8);
            float4 w3 = *(const float4*)(D1 + (size_t)k * 512 + j0 + 12);
#pragma unroll
            for (int i = 0; i < 4; i++) {
                float a = sh[(n0 + i) * SH + k];
                acc[i][0]  = fmaf(a, w0.x, acc[i][0]);
                acc[i][1]  = fmaf(a, w0.y, acc[i][1]);
                acc[i][2]  = fmaf(a, w0.z, acc[i][2]);
                acc[i][3]  = fmaf(a, w0.w, acc[i][3]);
                acc[i][4]  = fmaf(a, w1.x, acc[i][4]);
                acc[i][5]  = fmaf(a, w1.y, acc[i][5]);
                acc[i][6]  = fmaf(a, w1.z, acc[i][6]);
                acc[i][7]  = fmaf(a, w1.w, acc[i][7]);
                acc[i][8]  = fmaf(a, w2.x, acc[i][8]);
                acc[i][9]  = fmaf(a, w2.y, acc[i][9]);
                acc[i][10] = fmaf(a, w2.z, acc[i][10]);
                acc[i][11] = fmaf(a, w2.w, acc[i][11]);
                acc[i][12] = fmaf(a, w3.x, acc[i][12]);
                acc[i][13] = fmaf(a, w3.y, acc[i][13]);
                acc[i][14] = fmaf(a, w3.z, acc[i][14]);
                acc[i][15] = fmaf(a, w3.w, acc[i][15]);
            }
        }
#pragma unroll
        for (int j = 0; j < 16; j++) {
            float b = db1[j0 + j];
#pragma unroll
            for (int i = 0; i < 4; i++) {
                float v = acc[i][j] + b;
                st[(n0 + i) * ST + j0 + j] = v > 0.f ? v : 0.f;
            }
        }
    }
    __syncthreads();

    // ---- GEMM2: dh2 = st @ D2 + db2; residual into sh ----
    {
        const int n0 = ty * 4, j1 = tx * 4;
        float acc2[4][4];
#pragma unroll
        for (int i = 0; i < 4; i++)
#pragma unroll
            for (int j = 0; j < 4; j++) acc2[i][j] = 0.f;

#pragma unroll 4
        for (int k = 0; k < 512; k++) {
            float4 w = *(const float4*)(D2 + (size_t)k * H + j1);
#pragma unroll
            for (int i = 0; i < 4; i++) {
                float a = st[(n0 + i) * ST + k];
                acc2[i][0] = fmaf(a, w.x, acc2[i][0]);
                acc2[i][1] = fmaf(a, w.y, acc2[i][1]);
                acc2[i][2] = fmaf(a, w.z, acc2[i][2]);
                acc2[i][3] = fmaf(a, w.w, acc2[i][3]);
            }
        }
#pragma unroll
        for (int j = 0; j < 4; j++) {
            float b = db2[j1 + j];
#pragma unroll
            for (int i = 0; i < 4; i++) {
                int idx = (n0 + i) * SH + j1 + j;
                sh[idx] = sh[idx] + acc2[i][j] + b;  // h + dh2
            }
        }
    }
    __syncthreads();

    // ---- LN2 + write out ----
    {
        int n = tid >> 3, l = tid & 7;
        float* row = sh + n * SH;
        float s = 0.f;
        for (int c = l; c < H; c += 8) s += row[c];
        s += __shfl_xor_sync(~0u, s, 1);
        s += __shfl_xor_sync(~0u, s, 2);
        s += __shfl_xor_sync(~0u, s, 4);
        float mean = s * (1.f / H);
        float ss = 0.f;
        for (int c = l; c < H; c += 8) { float d = row[c] - mean; ss += d * d; }
        ss += __shfl_xor_sync(~0u, ss, 1);
        ss += __shfl_xor_sync(~0u, ss, 2);
        ss += __shfl_xor_sync(~0u, ss, 4);
        float rstd = rsqrtf(ss * (1.f / H) + EPS);
        float* orow = out + (nbase + n) * H;
        for (int c = l; c < H; c += 8)
            orow[c] = (row[c] - mean) * rstd * g2[c] + be2[c];
    }
}

// ---------------------------------------------------------------------------
extern "C" void kernel_launch(void* const* d_in, const int* in_sizes, int n_in,
                              void* d_out, int out_size) {
    const float* h_V  = (const float*)d_in[0];
    const float* h_E  = (const float*)d_in[1];
    const void*  eidx = (const void*)d_in[2];
    const float* W1 = (const float*)d_in[3];
    const float* b1 = (const float*)d_in[4];
    const float* W2 = (const float*)d_in[5];
    const float* b2 = (const float*)d_in[6];
    const float* W3 = (const float*)d_in[7];
    const float* b3 = (const float*)d_in[8];
    const float* D1 = (const float*)d_in[9];
    const float* db1 = (const float*)d_in[10];
    const float* D2 = (const float*)d_in[11];
    const float* db2 = (const float*)d_in[12];
    const float* g1 = (const float*)d_in[13];
    const float* be1 = (const float*)d_in[14];
    const float* g2 = (const float*)d_in[15];
    const float* be2 = (const float*)d_in[16];
    float* out = (float*)d_out;

    const size_t edge_smem = (size_t)(TILE_E * SE + 2 * TILE_E * SMSTR) * sizeof(float);
    const size_t node_smem = (size_t)(NT * SH + NT * ST) * sizeof(float);

    cudaFuncSetAttribute(edge_kernel, cudaFuncAttributeMaxDynamicSharedMemorySize, (int)edge_smem);
    cudaFuncSetAttribute(node_kernel, cudaFuncAttributeMaxDynamicSharedMemorySize, (int)node_smem);

    void* dh_ptr = nullptr;
    cudaGetSymbolAddress(&dh_ptr, g_dh);
    cudaMemsetAsync(dh_ptr, 0, sizeof(float) * (size_t)N_NODES * H, 0);

    detect_idx_kernel<<<1, 1>>>(eidx);
    edge_kernel<<<N_EDGES / TILE_E, 256, edge_smem>>>(h_E, eidx, W1, b1, W2, b2, W3, b3);
    node_kernel<<<N_NODES / NT, 256, node_smem>>>(h_V, D1, db1, D2, db2, g1, be1, g2, be2, out);
}

// round 4
// speedup vs baseline: 2.6002x; 2.6002x over previous
#include <cuda_runtime.h>
#include <cuda_bf16.h>
#include <cstdint>

#define N_NODES 100000
#define N_EDGES 800000
#define H 128
#define HE 256
#define EPS 1e-5f

// ---------------- edge kernel geometry ----------------
#define M_TILE 128          // edges per CTA
#define SA_STRIDE 264       // padded elems per A row (528B ≡ 16 mod 128)
#define SB_STRIDE 136       // padded elems per B row (272B ≡ 16 mod 128)
#define CHUNK_HALF 17408    // 64 rows * 136 * 2B
#define CHUNK_BYTES 34816   // hi + lo
#define OFF_BIAS 0
#define OFF_AHI  1536
#define OFF_ALO  (1536 + 67584)          // 69120
#define OFF_SB   (69120 + 67584)         // 136704
#define EDGE_SMEM (136704 + 2 * 34816)   // 206336

// ---------------- node kernel config ----------------
#define NT 32
#define SH 132
#define ST 516

// ---------------- globals (no allocation allowed) ----------------
__device__ float g_dh[(size_t)N_NODES * H];
__device__ int g_idx_is64;
// 8 weight chunks: L1 k0-255 -> chunks 0-3, L2 -> 4-5, L3 -> 6-7.
// chunk c at c*34816: hi [64][136] bf16, then lo [64][136] bf16.
__device__ __align__(1024) unsigned char g_B[8 * CHUNK_BYTES];

// ===========================================================================
// PTX helpers (baseline ISA only: sm_80-level)
// ===========================================================================
__device__ __forceinline__ uint32_t smem_u32(const void* p) {
    uint32_t a;
    asm("{ .reg .u64 t; cvta.to.shared.u64 t, %1; cvt.u32.u64 %0, t; }" : "=r"(a) : "l"(p));
    return a;
}
__device__ __forceinline__ void ldsm_x4(uint32_t* r, uint32_t addr) {
    asm volatile("ldmatrix.sync.aligned.m8n8.x4.shared.b16 {%0,%1,%2,%3}, [%4];"
                 : "=r"(r[0]), "=r"(r[1]), "=r"(r[2]), "=r"(r[3]) : "r"(addr));
}
__device__ __forceinline__ void ldsm_x4_t(uint32_t* r, uint32_t addr) {
    asm volatile("ldmatrix.sync.aligned.m8n8.x4.trans.shared.b16 {%0,%1,%2,%3}, [%4];"
                 : "=r"(r[0]), "=r"(r[1]), "=r"(r[2]), "=r"(r[3]) : "r"(addr));
}
__device__ __forceinline__ void mma16816(float* d, const uint32_t* a, uint32_t b0, uint32_t b1) {
    asm volatile("mma.sync.aligned.m16n8k16.row.col.f32.bf16.bf16.f32 "
                 "{%0,%1,%2,%3}, {%4,%5,%6,%7}, {%8,%9}, {%0,%1,%2,%3};"
                 : "+f"(d[0]), "+f"(d[1]), "+f"(d[2]), "+f"(d[3])
                 : "r"(a[0]), "r"(a[1]), "r"(a[2]), "r"(a[3]), "r"(b0), "r"(b1));
}
__device__ __forceinline__ void cp_async16(uint32_t saddr, const void* g) {
    asm volatile("cp.async.cg.shared.global [%0], [%1], 16;" :: "r"(saddr), "l"(g));
}
#define CP_COMMIT() asm volatile("cp.async.commit_group;")
#define CP_WAIT0()  asm volatile("cp.async.wait_group 0;" ::: "memory")

// split f32 -> (bf16 hi via truncation, bf16 lo residual), packed pairs
__device__ __forceinline__ void split_pack(float v0, float v1, uint32_t& hi, uint32_t& lo) {
    uint32_t u0 = __float_as_uint(v0), u1 = __float_as_uint(v1);
    hi = (u0 >> 16) | (u1 & 0xffff0000u);
    float f0 = __uint_as_float(u0 & 0xffff0000u);
    float f1 = __uint_as_float(u1 & 0xffff0000u);
    lo = (uint32_t)__bfloat16_as_ushort(__float2bfloat16(v0 - f0)) |
         ((uint32_t)__bfloat16_as_ushort(__float2bfloat16(v1 - f1)) << 16);
}

// ---------------------------------------------------------------------------
__global__ void detect_idx_kernel(const void* eidx) {
    const long long* p = (const long long*)eidx;
    int is64 = 1;
    for (int i = 0; i < 64; i++) {
        long long v = p[i];
        if (v < 0 || v >= N_NODES) { is64 = 0; break; }
    }
    g_idx_is64 = is64;
}

// ---------------------------------------------------------------------------
// Weight prep: keep natural [K][N] layout (ldmatrix.trans handles transpose),
// split into bf16 hi/lo, padded row stride 136.
// ---------------------------------------------------------------------------
__global__ void prep_weights_kernel(const float* __restrict__ W1,
                                    const float* __restrict__ W2,
                                    const float* __restrict__ W3) {
    int idx = blockIdx.x * 256 + threadIdx.x;   // 0 .. 65535
    int n = idx & 127;
    int krow = idx >> 7;                        // 0..511
    const float* W; int k, chunk;
    if (krow < 256)      { W = W1; k = krow;       chunk = krow >> 6; }
    else if (krow < 384) { W = W2; k = krow - 256; chunk = 4 + ((krow - 256) >> 6); }
    else                 { W = W3; k = krow - 384; chunk = 6 + ((krow - 384) >> 6); }
    float v = W[(size_t)k * 128 + n];
    uint32_t u = __float_as_uint(v);
    unsigned short hi = (unsigned short)(u >> 16);
    float fhi = __uint_as_float(u & 0xffff0000u);
    unsigned short lo = __bfloat16_as_ushort(__float2bfloat16(v - fhi));
    int kk = k & 63;
    size_t off = (size_t)chunk * CHUNK_BYTES + (size_t)(kk * SB_STRIDE + n) * 2;
    *(unsigned short*)(g_B + off) = hi;
    *(unsigned short*)(g_B + off + CHUNK_HALF) = lo;
}

// ===========================================================================
// Edge kernel: split-bf16 HMMA 3-layer MLP + scatter
// ===========================================================================
__global__ __launch_bounds__(256, 1)
void edge_mma_kernel(const float* __restrict__ hE, const void* __restrict__ eidx,
                     const float* __restrict__ b1, const float* __restrict__ b2,
                     const float* __restrict__ b3) {
    extern __shared__ char sm[];
    const uint32_t sb = smem_u32(sm);
    const int tid = threadIdx.x, wid = tid >> 5, lane = tid & 31;
    const long long ebase = (long long)blockIdx.x * M_TILE;

    // biases
    if (tid < 128) {
        ((float*)sm)[tid] = b1[tid];
        ((float*)sm)[128 + tid] = b2[tid];
        ((float*)sm)[256 + tid] = b3[tid];
    }

    // kick off B chunk 0 while we stage A
    for (int i = tid; i < 2176; i += 256)
        cp_async16(sb + OFF_SB + i * 16, g_B + i * 16);
    CP_COMMIT();

    // stage layer-1 A: h_E [128 x 256] f32 -> split bf16 hi/lo, padded stride
    {
        const float4* gE = (const float4*)(hE + ebase * HE);
        char* aHi = sm + OFF_AHI;
        char* aLo = sm + OFF_ALO;
        for (int i = tid; i < 128 * 64; i += 256) {
            int row = i >> 6, c4 = i & 63;
            float4 v = gE[i];
            uint32_t h01, l01, h23, l23;
            split_pack(v.x, v.y, h01, l01);
            split_pack(v.z, v.w, h23, l23);
            uint32_t off = (uint32_t)(row * SA_STRIDE + c4 * 4) * 2;
            *(uint2*)(aHi + off) = make_uint2(h01, h23);
            *(uint2*)(aLo + off) = make_uint2(l01, l23);
        }
    }
    CP_WAIT0();
    __syncthreads();

    // fragment address components
    const int mrow = lane & 7, mid = lane >> 3;
    const uint32_t a_row_off =
        (uint32_t)((wid * 16 + (mid & 1) * 8 + mrow) * SA_STRIDE + (mid >> 1) * 8) * 2;
    const uint32_t b_frag_off =
        (uint32_t)(((mid & 1) * 8 + mrow) * SB_STRIDE + (mid >> 1) * 8) * 2;
    const int bq = 2 * (lane & 3);

    float acc[16][4];
    uint32_t aH[8][4], aL[8][4];
    float* sBias = (float*)sm;

#define ZERO_ACC() do { \
    _Pragma("unroll") for (int t = 0; t < 16; t++) \
        { acc[t][0] = 0.f; acc[t][1] = 0.f; acc[t][2] = 0.f; acc[t][3] = 0.f; } } while (0)

#define PREFETCH(c) do { \
    const unsigned char* _src = g_B + (c) * CHUNK_BYTES; \
    uint32_t _dst = sb + OFF_SB + ((c) & 1) * CHUNK_BYTES; \
    for (int i = tid; i < 2176; i += 256) cp_async16(_dst + i * 16, _src + i * 16); \
    CP_COMMIT(); } while (0)

    // one k16 step: 18 ldmatrix + 48 mma (3-term split), A frags given
#define KSTEP(fAh, fAl, sBhi, sBlo, brow) do { \
    _Pragma("unroll") for (int p = 0; p < 8; p++) { \
        uint32_t bh[4], bl[4]; \
        uint32_t _bo = b_frag_off + (brow) + (uint32_t)(p * 16) * 2; \
        ldsm_x4_t(bh, (sBhi) + _bo); \
        ldsm_x4_t(bl, (sBlo) + _bo); \
        mma16816(acc[2 * p],     fAh, bh[0], bh[1]); \
        mma16816(acc[2 * p],     fAh, bl[0], bl[1]); \
        mma16816(acc[2 * p],     fAl, bh[0], bh[1]); \
        mma16816(acc[2 * p + 1], fAh, bh[2], bh[3]); \
        mma16816(acc[2 * p + 1], fAh, bl[2], bl[3]); \
        mma16816(acc[2 * p + 1], fAl, bh[2], bh[3]); \
    } } while (0)

    // layer-1 chunk: A fragments from smem
#define COMPUTE_SMEM(c) do { \
    uint32_t _sBhi = sb + OFF_SB + ((c) & 1) * CHUNK_BYTES; \
    uint32_t _sBlo = _sBhi + CHUNK_HALF; \
    _Pragma("unroll") for (int js = 0; js < 4; js++) { \
        uint32_t fAh[4], fAl[4]; \
        uint32_t _acol = (uint32_t)((c) * 64 + js * 16) * 2; \
        ldsm_x4(fAh, sb + OFF_AHI + a_row_off + _acol); \
        ldsm_x4(fAl, sb + OFF_ALO + a_row_off + _acol); \
        KSTEP(fAh, fAl, _sBhi, _sBlo, (uint32_t)(js * 16 * SB_STRIDE) * 2); \
    } } while (0)

    // layer-2/3 chunk: A fragments from registers, JB = compile-time literal
#define COMPUTE_REG(JB, c) do { \
    uint32_t _sBhi = sb + OFF_SB + ((c) & 1) * CHUNK_BYTES; \
    uint32_t _sBlo = _sBhi + CHUNK_HALF; \
    _Pragma("unroll") for (int js = 0; js < 4; js++) { \
        KSTEP(aH[(JB) + js], aL[(JB) + js], _sBhi, _sBlo, (uint32_t)(js * 16 * SB_STRIDE) * 2); \
    } } while (0)

    // bias + relu + split into next-layer A fragments (in registers)
#define EPILOGUE_RELU(biasBase) do { \
    _Pragma("unroll") for (int t = 0; t < 16; t++) { \
        float2 bb = *(float2*)&sBias[(biasBase) + t * 8 + bq]; \
        float v0 = fmaxf(acc[t][0] + bb.x, 0.f); \
        float v1 = fmaxf(acc[t][1] + bb.y, 0.f); \
        float v2 = fmaxf(acc[t][2] + bb.x, 0.f); \
        float v3 = fmaxf(acc[t][3] + bb.y, 0.f); \
        uint32_t h01, l01, h23, l23; \
        split_pack(v0, v1, h01, l01); \
        split_pack(v2, v3, h23, l23); \
        int _j = t >> 1, _b = (t & 1) * 2; \
        aH[_j][_b] = h01; aH[_j][_b + 1] = h23; \
        aL[_j][_b] = l01; aL[_j][_b + 1] = l23; \
    } } while (0)

    ZERO_ACC();
    PREFETCH(1); COMPUTE_SMEM(0); CP_WAIT0(); __syncthreads();
    PREFETCH(2); COMPUTE_SMEM(1); CP_WAIT0(); __syncthreads();
    PREFETCH(3); COMPUTE_SMEM(2); CP_WAIT0(); __syncthreads();
    PREFETCH(4); COMPUTE_SMEM(3); CP_WAIT0(); __syncthreads();
    EPILOGUE_RELU(0); ZERO_ACC();
    PREFETCH(5); COMPUTE_REG(0, 4); CP_WAIT0(); __syncthreads();
    PREFETCH(6); COMPUTE_REG(4, 5); CP_WAIT0(); __syncthreads();
    EPILOGUE_RELU(128); ZERO_ACC();
    PREFETCH(7); COMPUTE_REG(0, 6); CP_WAIT0(); __syncthreads();
    COMPUTE_REG(4, 7); __syncthreads();

    // ---- layer-3 epilogue: bias -> padded smem -> coalesced atomic scatter ----
    {
        float* sOut = (float*)(sm + OFF_AHI);   // 128 x 132 f32 (A region dead)
        int row0 = wid * 16 + (lane >> 2);
#pragma unroll
        for (int t = 0; t < 16; t++) {
            float2 bb = *(float2*)&sBias[256 + t * 8 + bq];
            float v0 = acc[t][0] + bb.x, v1 = acc[t][1] + bb.y;
            float v2 = acc[t][2] + bb.x, v3 = acc[t][3] + bb.y;
            *(float2*)&sOut[row0 * 132 + t * 8 + bq] = make_float2(v0, v1);
            *(float2*)&sOut[(row0 + 8) * 132 + t * 8 + bq] = make_float2(v2, v3);
        }
        __syncthreads();

        const int is64 = g_idx_is64;
        for (int e = wid; e < 128; e += 8) {
            long long s = is64 ? ((const long long*)eidx)[ebase + e]
                               : (long long)((const int*)eidx)[ebase + e];
            float* dst = g_dh + (size_t)s * H;
            const float* srow = sOut + e * 132;
#pragma unroll
            for (int q = 0; q < 4; q++) {
                int col = lane + q * 32;
                atomicAdd(dst + col, srow[col]);
            }
        }
    }
#undef ZERO_ACC
#undef PREFETCH
#undef KSTEP
#undef COMPUTE_SMEM
#undef COMPUTE_REG
#undef EPILOGUE_RELU
}

// ===========================================================================
// Node kernel (fp32, unchanged from passing R2)
// ===========================================================================
__global__ __launch_bounds__(256, 1) void node_kernel(
    const float* __restrict__ hV,
    const float* __restrict__ D1, const float* __restrict__ db1,
    const float* __restrict__ D2, const float* __restrict__ db2,
    const float* __restrict__ g1, const float* __restrict__ be1,
    const float* __restrict__ g2, const float* __restrict__ be2,
    float* __restrict__ out) {
    extern __shared__ float smem[];
    float* sh = smem;
    float* st = sh + NT * SH;

    const int tid = threadIdx.x;
    const long long nbase = (long long)blockIdx.x * NT;

    {
        const float4* gV = (const float4*)(hV + nbase * H);
        const float4* gD = (const float4*)(g_dh + nbase * H);
        for (int i = tid; i < NT * (H / 4); i += 256) {
            int n = i >> 5, c = i & 31;
            float4 v = gV[(size_t)n * 32 + c];
            float4 d = gD[(size_t)n * 32 + c];
            float* dst = &sh[n * SH + c * 4];
            dst[0] = v.x + d.x / 30.0f;
            dst[1] = v.y + d.y / 30.0f;
            dst[2] = v.z + d.z / 30.0f;
            dst[3] = v.w + d.w / 30.0f;
        }
    }
    __syncthreads();

    {
        int n = tid >> 3, l = tid & 7;
        float* row = sh + n * SH;
        float s = 0.f;
        for (int c = l; c < H; c += 8) s += row[c];
        s += __shfl_xor_sync(~0u, s, 1);
        s += __shfl_xor_sync(~0u, s, 2);
        s += __shfl_xor_sync(~0u, s, 4);
        float mean = s * (1.f / H);
        float ss = 0.f;
        for (int c = l; c < H; c += 8) { float d = row[c] - mean; ss += d * d; }
        ss += __shfl_xor_sync(~0u, ss, 1);
        ss += __shfl_xor_sync(~0u, ss, 2);
        ss += __shfl_xor_sync(~0u, ss, 4);
        float rstd = rsqrtf(ss * (1.f / H) + EPS);
        for (int c = l; c < H; c += 8)
            row[c] = (row[c] - mean) * rstd * g1[c] + be1[c];
    }
    __syncthreads();

    const int tx = tid & 31, ty = tid >> 5;

    {
        const int n0 = ty * 4, j0 = tx * 16;
        float acc[4][16];
#pragma unroll
        for (int i = 0; i < 4; i++)
#pragma unroll
            for (int j = 0; j < 16; j++) acc[i][j] = 0.f;

#pragma unroll 2
        for (int k = 0; k < H; k++) {
            float4 w0 = *(const float4*)(D1 + (size_t)k * 512 + j0);
            float4 w1 = *(const float4*)(D1 + (size_t)k * 512 + j0 + 4);
            float4 w2 = *(const float4*)(D1 + (size_t)k * 512 + j0 + 8);
            float4 w3 = *(const float4*)(D1 + (size_t)k * 512 + j0 + 12);
#pragma unroll
            for (int i = 0; i < 4; i++) {
                float a = sh[(n0 + i) * SH + k];
                acc[i][0]  = fmaf(a, w0.x, acc[i][0]);
                acc[i][1]  = fmaf(a, w0.y, acc[i][1]);
                acc[i][2]  = fmaf(a, w0.z, acc[i][2]);
                acc[i][3]  = fmaf(a, w0.w, acc[i][3]);
                acc[i][4]  = fmaf(a, w1.x, acc[i][4]);
                acc[i][5]  = fmaf(a, w1.y, acc[i][5]);
                acc[i][6]  = fmaf(a, w1.z, acc[i][6]);
                acc[i][7]  = fmaf(a, w1.w, acc[i][7]);
                acc[i][8]  = fmaf(a, w2.x, acc[i][8]);
                acc[i][9]  = fmaf(a, w2.y, acc[i][9]);
                acc[i][10] = fmaf(a, w2.z, acc[i][10]);
                acc[i][11] = fmaf(a, w2.w, acc[i][11]);
                acc[i][12] = fmaf(a, w3.x, acc[i][12]);
                acc[i][13] = fmaf(a, w3.y, acc[i][13]);
                acc[i][14] = fmaf(a, w3.z, acc[i][14]);
                acc[i][15] = fmaf(a, w3.w, acc[i][15]);
            }
        }
#pragma unroll
        for (int j = 0; j < 16; j++) {
            float b = db1[j0 + j];
#pragma unroll
            for (int i = 0; i < 4; i++) {
                float v = acc[i][j] + b;
                st[(n0 + i) * ST + j0 + j] = v > 0.f ? v : 0.f;
            }
        }
    }
    __syncthreads();

    {
        const int n0 = ty * 4, j1 = tx * 4;
        float acc2[4][4];
#pragma unroll
        for (int i = 0; i < 4; i++)
#pragma unroll
            for (int j = 0; j < 4; j++) acc2[i][j] = 0.f;

#pragma unroll 4
        for (int k = 0; k < 512; k++) {
            float4 w = *(const float4*)(D2 + (size_t)k * H + j1);
#pragma unroll
            for (int i = 0; i < 4; i++) {
                float a = st[(n0 + i) * ST + k];
                acc2[i][0] = fmaf(a, w.x, acc2[i][0]);
                acc2[i][1] = fmaf(a, w.y, acc2[i][1]);
                acc2[i][2] = fmaf(a, w.z, acc2[i][2]);
                acc2[i][3] = fmaf(a, w.w, acc2[i][3]);
            }
        }
#pragma unroll
        for (int j = 0; j < 4; j++) {
            float b = db2[j1 + j];
#pragma unroll
            for (int i = 0; i < 4; i++) {
                int idx = (n0 + i) * SH + j1 + j;
                sh[idx] = sh[idx] + acc2[i][j] + b;
            }
        }
    }
    __syncthreads();

    {
        int n = tid >> 3, l = tid & 7;
        float* row = sh + n * SH;
        float s = 0.f;
        for (int c = l; c < H; c += 8) s += row[c];
        s += __shfl_xor_sync(~0u, s, 1);
        s += __shfl_xor_sync(~0u, s, 2);
        s += __shfl_xor_sync(~0u, s, 4);
        float mean = s * (1.f / H);
        float ss = 0.f;
        for (int c = l; c < H; c += 8) { float d = row[c] - mean; ss += d * d; }
        ss += __shfl_xor_sync(~0u, ss, 1);
        ss += __shfl_xor_sync(~0u, ss, 2);
        ss += __shfl_xor_sync(~0u, ss, 4);
        float rstd = rsqrtf(ss * (1.f / H) + EPS);
        float* orow = out + (nbase + n) * H;
        for (int c = l; c < H; c += 8)
            orow[c] = (row[c] - mean) * rstd * g2[c] + be2[c];
    }
}

// ===========================================================================
extern "C" void kernel_launch(void* const* d_in, const int* in_sizes, int n_in,
                              void* d_out, int out_size) {
    const float* h_V  = (const float*)d_in[0];
    const float* h_E  = (const float*)d_in[1];
    const void*  eidx = (const void*)d_in[2];
    const float* W1 = (const float*)d_in[3];
    const float* b1 = (const float*)d_in[4];
    const float* W2 = (const float*)d_in[5];
    const float* b2 = (const float*)d_in[6];
    const float* W3 = (const float*)d_in[7];
    const float* b3 = (const float*)d_in[8];
    const float* D1 = (const float*)d_in[9];
    const float* db1 = (const float*)d_in[10];
    const float* D2 = (const float*)d_in[11];
    const float* db2 = (const float*)d_in[12];
    const float* g1 = (const float*)d_in[13];
    const float* be1 = (const float*)d_in[14];
    const float* g2 = (const float*)d_in[15];
    const float* be2 = (const float*)d_in[16];
    float* out = (float*)d_out;

    const size_t node_smem = (size_t)(NT * SH + NT * ST) * sizeof(float);

    cudaFuncSetAttribute(edge_mma_kernel, cudaFuncAttributeMaxDynamicSharedMemorySize, EDGE_SMEM);
    cudaFuncSetAttribute(node_kernel, cudaFuncAttributeMaxDynamicSharedMemorySize, (int)node_smem);

    void* dh_ptr = nullptr;
    cudaGetSymbolAddress(&dh_ptr, g_dh);
    cudaMemsetAsync(dh_ptr, 0, sizeof(float) * (size_t)N_NODES * H, 0);

    detect_idx_kernel<<<1, 1>>>(eidx);
    prep_weights_kernel<<<256, 256>>>(W1, W2, W3);
    edge_mma_kernel<<<N_EDGES / M_TILE, 256, EDGE_SMEM>>>(h_E, eidx, b1, b2, b3);
    node_kernel<<<N_NODES / NT, 256, node_smem>>>(h_V, D1, db1, D2, db2, g1, be1, g2, be2, out);
}

// round 5
// speedup vs baseline: 4.4966x; 1.7294x over previous
#include <cuda_runtime.h>
#include <cuda_bf16.h>
#include <cstdint>

#define N_NODES 100000
#define N_EDGES 800000
#define H 128
#define HE 256
#define EPS 1e-5f

// ---------------- edge kernel geometry ----------------
#define M_TILE 128
#define SA_STRIDE 264       // padded elems per A row (528B ≡ 16 mod 128)
#define SB_STRIDE 136       // padded elems per B row (272B ≡ 16 mod 128)
#define CHUNK_HALF 17408    // 64 rows * 136 * 2B
#define CHUNK_BYTES 34816
#define OFF_BIAS 0
#define OFF_AHI  1536
#define OFF_ALO  (1536 + 67584)
#define OFF_SB   (69120 + 67584)
#define EDGE_SMEM (136704 + 2 * 34816)

// ---------------- node kernel geometry ----------------
#define OFF_NBIAS 0                       // 1152 floats = 4608 B
#define OFF_A1HI  4608
#define OFF_A1LO  (4608 + 34816)
#define OFF_NB    (4608 + 69632)          // 74240
#define NODE_SMEM (OFF_NB + 2 * 34816)    // 143872

// ---------------- globals ----------------
__device__ float g_dh[(size_t)N_NODES * H];
__device__ int g_idx_is64;
// units 0-7: edge W1/W2/W3 chunks. units 8-23: node weights in STREAM ORDER:
// for c in 0..3: D1[k0-63, n 128c..], D1[k64-127, ...], D2[k128c+0-63], D2[k128c+64-127]
__device__ __align__(1024) unsigned char g_B[24 * CHUNK_BYTES];

// ===========================================================================
// PTX helpers (baseline ISA only)
// ===========================================================================
__device__ __forceinline__ uint32_t smem_u32(const void* p) {
    uint32_t a;
    asm("{ .reg .u64 t; cvta.to.shared.u64 t, %1; cvt.u32.u64 %0, t; }" : "=r"(a) : "l"(p));
    return a;
}
__device__ __forceinline__ void ldsm_x4(uint32_t* r, uint32_t addr) {
    asm volatile("ldmatrix.sync.aligned.m8n8.x4.shared.b16 {%0,%1,%2,%3}, [%4];"
                 : "=r"(r[0]), "=r"(r[1]), "=r"(r[2]), "=r"(r[3]) : "r"(addr));
}
__device__ __forceinline__ void ldsm_x4_t(uint32_t* r, uint32_t addr) {
    asm volatile("ldmatrix.sync.aligned.m8n8.x4.trans.shared.b16 {%0,%1,%2,%3}, [%4];"
                 : "=r"(r[0]), "=r"(r[1]), "=r"(r[2]), "=r"(r[3]) : "r"(addr));
}
__device__ __forceinline__ void mma16816(float* d, const uint32_t* a, uint32_t b0, uint32_t b1) {
    asm volatile("mma.sync.aligned.m16n8k16.row.col.f32.bf16.bf16.f32 "
                 "{%0,%1,%2,%3}, {%4,%5,%6,%7}, {%8,%9}, {%0,%1,%2,%3};"
                 : "+f"(d[0]), "+f"(d[1]), "+f"(d[2]), "+f"(d[3])
                 : "r"(a[0]), "r"(a[1]), "r"(a[2]), "r"(a[3]), "r"(b0), "r"(b1));
}
__device__ __forceinline__ void cp_async16(uint32_t saddr, const void* g) {
    asm volatile("cp.async.cg.shared.global [%0], [%1], 16;" :: "r"(saddr), "l"(g));
}
#define CP_COMMIT() asm volatile("cp.async.commit_group;")
#define CP_WAIT0()  asm volatile("cp.async.wait_group 0;" ::: "memory")

__device__ __forceinline__ void split_pack(float v0, float v1, uint32_t& hi, uint32_t& lo) {
    uint32_t u0 = __float_as_uint(v0), u1 = __float_as_uint(v1);
    hi = (u0 >> 16) | (u1 & 0xffff0000u);
    float f0 = __uint_as_float(u0 & 0xffff0000u);
    float f1 = __uint_as_float(u1 & 0xffff0000u);
    lo = (uint32_t)__bfloat16_as_ushort(__float2bfloat16(v0 - f0)) |
         ((uint32_t)__bfloat16_as_ushort(__float2bfloat16(v1 - f1)) << 16);
}
__device__ __forceinline__ void split_store(const float* W_like, float v,
                                            unsigned char* hiP, unsigned char* loP) {
    uint32_t u = __float_as_uint(v);
    *(unsigned short*)hiP = (unsigned short)(u >> 16);
    float fhi = __uint_as_float(u & 0xffff0000u);
    *(unsigned short*)loP = __bfloat16_as_ushort(__float2bfloat16(v - fhi));
}

// shared k16 step: ACC = target acc array (float[..][4]), 3-term split MMA over N=128
#define KSTEP_G(ACC, fAh, fAl, sBhi, sBlo, brow) do { \
    _Pragma("unroll") for (int p = 0; p < 8; p++) { \
        uint32_t bh[4], bl[4]; \
        uint32_t _bo = b_frag_off + (brow) + (uint32_t)(p * 16) * 2; \
        ldsm_x4_t(bh, (sBhi) + _bo); \
        ldsm_x4_t(bl, (sBlo) + _bo); \
        mma16816((ACC)[2 * p],     fAh, bh[0], bh[1]); \
        mma16816((ACC)[2 * p],     fAh, bl[0], bl[1]); \
        mma16816((ACC)[2 * p],     fAl, bh[0], bh[1]); \
        mma16816((ACC)[2 * p + 1], fAh, bh[2], bh[3]); \
        mma16816((ACC)[2 * p + 1], fAh, bl[2], bl[3]); \
        mma16816((ACC)[2 * p + 1], fAl, bh[2], bh[3]); \
    } } while (0)

// ---------------------------------------------------------------------------
__global__ void detect_idx_kernel(const void* eidx) {
    const long long* p = (const long long*)eidx;
    int is64 = 1;
    for (int i = 0; i < 64; i++) {
        long long v = p[i];
        if (v < 0 || v >= N_NODES) { is64 = 0; break; }
    }
    g_idx_is64 = is64;
}

// ---------------------------------------------------------------------------
// Weight prep: W1/W2/W3 (edge) + D1/D2 (node) -> split hi/lo padded chunk units
// ---------------------------------------------------------------------------
__global__ void prep_weights_kernel(const float* __restrict__ W1,
                                    const float* __restrict__ W2,
                                    const float* __restrict__ W3,
                                    const float* __restrict__ D1,
                                    const float* __restrict__ D2) {
    int idx = blockIdx.x * 256 + threadIdx.x;    // 0 .. 196607
    float v; int unit, kk, n;
    if (idx < 65536) {
        n = idx & 127;
        int krow = idx >> 7;
        const float* W; int k;
        if (krow < 256)      { W = W1; k = krow;       unit = krow >> 6; }
        else if (krow < 384) { W = W2; k = krow - 256; unit = 4 + ((krow - 256) >> 6); }
        else                 { W = W3; k = krow - 384; unit = 6 + ((krow - 384) >> 6); }
        v = W[(size_t)k * 128 + n];
        kk = k & 63;
    } else if (idx < 131072) {
        int i = idx - 65536;                     // D1: 128 x 512
        int k = i >> 9, n512 = i & 511;
        int c = n512 >> 7; n = n512 & 127;
        int half = k >> 6; kk = k & 63;
        unit = 8 + 4 * c + half;
        v = D1[(size_t)k * 512 + n512];
    } else {
        int i = idx - 131072;                    // D2: 512 x 128
        int k = i >> 7; n = i & 127;
        int c = k >> 7, krem = k & 127;
        int half = krem >> 6; kk = krem & 63;
        unit = 8 + 4 * c + 2 + half;
        v = D2[(size_t)k * 128 + n];
    }
    size_t off = (size_t)unit * CHUNK_BYTES + (size_t)(kk * SB_STRIDE + n) * 2;
    split_store(nullptr, v, g_B + off, g_B + off + CHUNK_HALF);
}

// ===========================================================================
// Edge kernel (unchanged from passing R4)
// ===========================================================================
__global__ __launch_bounds__(256, 1)
void edge_mma_kernel(const float* __restrict__ hE, const void* __restrict__ eidx,
                     const float* __restrict__ b1, const float* __restrict__ b2,
                     const float* __restrict__ b3) {
    extern __shared__ char sm[];
    const uint32_t sb = smem_u32(sm);
    const int tid = threadIdx.x, wid = tid >> 5, lane = tid & 31;
    const long long ebase = (long long)blockIdx.x * M_TILE;

    if (tid < 128) {
        ((float*)sm)[tid] = b1[tid];
        ((float*)sm)[128 + tid] = b2[tid];
        ((float*)sm)[256 + tid] = b3[tid];
    }

    for (int i = tid; i < 2176; i += 256)
        cp_async16(sb + OFF_SB + i * 16, g_B + i * 16);
    CP_COMMIT();

    {
        const float4* gE = (const float4*)(hE + ebase * HE);
        char* aHi = sm + OFF_AHI;
        char* aLo = sm + OFF_ALO;
        for (int i = tid; i < 128 * 64; i += 256) {
            int row = i >> 6, c4 = i & 63;
            float4 v = gE[i];
            uint32_t h01, l01, h23, l23;
            split_pack(v.x, v.y, h01, l01);
            split_pack(v.z, v.w, h23, l23);
            uint32_t off = (uint32_t)(row * SA_STRIDE + c4 * 4) * 2;
            *(uint2*)(aHi + off) = make_uint2(h01, h23);
            *(uint2*)(aLo + off) = make_uint2(l01, l23);
        }
    }
    CP_WAIT0();
    __syncthreads();

    const int mrow = lane & 7, mid = lane >> 3;
    const uint32_t a_row_off =
        (uint32_t)((wid * 16 + (mid & 1) * 8 + mrow) * SA_STRIDE + (mid >> 1) * 8) * 2;
    const uint32_t b_frag_off =
        (uint32_t)(((mid & 1) * 8 + mrow) * SB_STRIDE + (mid >> 1) * 8) * 2;
    const int bq = 2 * (lane & 3);

    float acc[16][4];
    uint32_t aH[8][4], aL[8][4];
    float* sBias = (float*)sm;

#define ZERO_ACC() do { \
    _Pragma("unroll") for (int t = 0; t < 16; t++) \
        { acc[t][0] = 0.f; acc[t][1] = 0.f; acc[t][2] = 0.f; acc[t][3] = 0.f; } } while (0)

#define PREFETCH(c) do { \
    const unsigned char* _src = g_B + (c) * CHUNK_BYTES; \
    uint32_t _dst = sb + OFF_SB + ((c) & 1) * CHUNK_BYTES; \
    for (int i = tid; i < 2176; i += 256) cp_async16(_dst + i * 16, _src + i * 16); \
    CP_COMMIT(); } while (0)

#define COMPUTE_SMEM(c) do { \
    uint32_t _sBhi = sb + OFF_SB + ((c) & 1) * CHUNK_BYTES; \
    uint32_t _sBlo = _sBhi + CHUNK_HALF; \
    _Pragma("unroll") for (int js = 0; js < 4; js++) { \
        uint32_t fAh[4], fAl[4]; \
        uint32_t _acol = (uint32_t)((c) * 64 + js * 16) * 2; \
        ldsm_x4(fAh, sb + OFF_AHI + a_row_off + _acol); \
        ldsm_x4(fAl, sb + OFF_ALO + a_row_off + _acol); \
        KSTEP_G(acc, fAh, fAl, _sBhi, _sBlo, (uint32_t)(js * 16 * SB_STRIDE) * 2); \
    } } while (0)

#define COMPUTE_REG(JB, c) do { \
    uint32_t _sBhi = sb + OFF_SB + ((c) & 1) * CHUNK_BYTES; \
    uint32_t _sBlo = _sBhi + CHUNK_HALF; \
    _Pragma("unroll") for (int js = 0; js < 4; js++) { \
        KSTEP_G(acc, aH[(JB) + js], aL[(JB) + js], _sBhi, _sBlo, (uint32_t)(js * 16 * SB_STRIDE) * 2); \
    } } while (0)

#define EPILOGUE_RELU(biasBase) do { \
    _Pragma("unroll") for (int t = 0; t < 16; t++) { \
        float2 bb = *(float2*)&sBias[(biasBase) + t * 8 + bq]; \
        float v0 = fmaxf(acc[t][0] + bb.x, 0.f); \
        float v1 = fmaxf(acc[t][1] + bb.y, 0.f); \
        float v2 = fmaxf(acc[t][2] + bb.x, 0.f); \
        float v3 = fmaxf(acc[t][3] + bb.y, 0.f); \
        uint32_t h01, l01, h23, l23; \
        split_pack(v0, v1, h01, l01); \
        split_pack(v2, v3, h23, l23); \
        int _j = t >> 1, _b = (t & 1) * 2; \
        aH[_j][_b] = h01; aH[_j][_b + 1] = h23; \
        aL[_j][_b] = l01; aL[_j][_b + 1] = l23; \
    } } while (0)

    ZERO_ACC();
    PREFETCH(1); COMPUTE_SMEM(0); CP_WAIT0(); __syncthreads();
    PREFETCH(2); COMPUTE_SMEM(1); CP_WAIT0(); __syncthreads();
    PREFETCH(3); COMPUTE_SMEM(2); CP_WAIT0(); __syncthreads();
    PREFETCH(4); COMPUTE_SMEM(3); CP_WAIT0(); __syncthreads();
    EPILOGUE_RELU(0); ZERO_ACC();
    PREFETCH(5); COMPUTE_REG(0, 4); CP_WAIT0(); __syncthreads();
    PREFETCH(6); COMPUTE_REG(4, 5); CP_WAIT0(); __syncthreads();
    EPILOGUE_RELU(128); ZERO_ACC();
    PREFETCH(7); COMPUTE_REG(0, 6); CP_WAIT0(); __syncthreads();
    COMPUTE_REG(4, 7); __syncthreads();

    {
        float* sOut = (float*)(sm + OFF_AHI);
        int row0 = wid * 16 + (lane >> 2);
#pragma unroll
        for (int t = 0; t < 16; t++) {
            float2 bb = *(float2*)&sBias[256 + t * 8 + bq];
            float v0 = acc[t][0] + bb.x, v1 = acc[t][1] + bb.y;
            float v2 = acc[t][2] + bb.x, v3 = acc[t][3] + bb.y;
            *(float2*)&sOut[row0 * 132 + t * 8 + bq] = make_float2(v0, v1);
            *(float2*)&sOut[(row0 + 8) * 132 + t * 8 + bq] = make_float2(v2, v3);
        }
        __syncthreads();

        const int is64 = g_idx_is64;
        for (int e = wid; e < 128; e += 8) {
            long long s = is64 ? ((const long long*)eidx)[ebase + e]
                               : (long long)((const int*)eidx)[ebase + e];
            float* dst = g_dh + (size_t)s * H;
            const float* srow = sOut + e * 132;
#pragma unroll
            for (int q = 0; q < 4; q++) {
                int col = lane + q * 32;
                atomicAdd(dst + col, srow[col]);
            }
        }
    }
#undef ZERO_ACC
#undef PREFETCH
#undef COMPUTE_SMEM
#undef COMPUTE_REG
#undef EPILOGUE_RELU
}

// ===========================================================================
// Node kernel: split-bf16 HMMA FFN, 128 nodes/CTA, LN in fragment registers
// ===========================================================================
__global__ __launch_bounds__(256, 1)
void node_mma_kernel(const float* __restrict__ hV,
                     const float* __restrict__ db1, const float* __restrict__ db2,
                     const float* __restrict__ g1, const float* __restrict__ be1,
                     const float* __restrict__ g2, const float* __restrict__ be2,
                     float* __restrict__ out) {
    extern __shared__ char sm[];
    const uint32_t sb = smem_u32(sm);
    const int tid = threadIdx.x, wid = tid >> 5, lane = tid & 31;
    const long long nbase = (long long)blockIdx.x * 128;

    float* sB = (float*)sm;   // [0,512): db1, [512,640): db2, [640,768): g1,
                              // [768,896): be1, [896,1024): g2, [1024,1152): be2
    for (int i = tid; i < 512; i += 256) sB[i] = db1[i];
    if (tid < 128) {
        sB[512 + tid] = db2[tid];
        sB[640 + tid] = g1[tid];  sB[768 + tid] = be1[tid];
        sB[896 + tid] = g2[tid];  sB[1024 + tid] = be2[tid];
    }

#define PREFETCH_N(s) do { \
    const unsigned char* _src = g_B + (8 + (s)) * CHUNK_BYTES; \
    uint32_t _dst = sb + OFF_NB + ((s) & 1) * CHUNK_BYTES; \
    for (int i = tid; i < 2176; i += 256) cp_async16(_dst + i * 16, _src + i * 16); \
    CP_COMMIT(); } while (0)

    PREFETCH_N(0);

    const int mrow = lane & 7, mid = lane >> 3;
    const uint32_t a_row_off =
        (uint32_t)((wid * 16 + (mid & 1) * 8 + mrow) * SB_STRIDE + (mid >> 1) * 8) * 2;
    const uint32_t b_frag_off =
        (uint32_t)(((mid & 1) * 8 + mrow) * SB_STRIDE + (mid >> 1) * 8) * 2;
    const int bq = 2 * (lane & 3);
    const int r0 = wid * 16 + (lane >> 2);         // local row (c0,c1); r0+8 for c2,c3
    const long long gr0 = nbase + r0, gr1 = gr0 + 8;
    const bool ok0 = gr0 < N_NODES, ok1 = gr1 < N_NODES;

    // ---- load x = hV + dh/30 in fragment layout; LN1 in registers ----
    {
        float x[16][4];
#pragma unroll
        for (int t = 0; t < 16; t++) {
            int col = t * 8 + bq;
            if (ok0) {
                float2 v = *(const float2*)(hV + gr0 * H + col);
                float2 d = *(const float2*)(g_dh + gr0 * H + col);
                x[t][0] = v.x + d.x * (1.f / 30.f);
                x[t][1] = v.y + d.y * (1.f / 30.f);
            } else { x[t][0] = 0.f; x[t][1] = 0.f; }
            if (ok1) {
                float2 v = *(const float2*)(hV + gr1 * H + col);
                float2 d = *(const float2*)(g_dh + gr1 * H + col);
                x[t][2] = v.x + d.x * (1.f / 30.f);
                x[t][3] = v.y + d.y * (1.f / 30.f);
            } else { x[t][2] = 0.f; x[t][3] = 0.f; }
        }
        float s0 = 0.f, s1 = 0.f;
#pragma unroll
        for (int t = 0; t < 16; t++) { s0 += x[t][0] + x[t][1]; s1 += x[t][2] + x[t][3]; }
        s0 += __shfl_xor_sync(~0u, s0, 1); s0 += __shfl_xor_sync(~0u, s0, 2);
        s1 += __shfl_xor_sync(~0u, s1, 1); s1 += __shfl_xor_sync(~0u, s1, 2);
        float m0 = s0 * (1.f / H), m1 = s1 * (1.f / H);
        float q0 = 0.f, q1 = 0.f;
#pragma unroll
        for (int t = 0; t < 16; t++) {
            float d0 = x[t][0] - m0, d1 = x[t][1] - m0;
            float d2 = x[t][2] - m1, d3 = x[t][3] - m1;
            q0 += d0 * d0 + d1 * d1; q1 += d2 * d2 + d3 * d3;
        }
        q0 += __shfl_xor_sync(~0u, q0, 1); q0 += __shfl_xor_sync(~0u, q0, 2);
        q1 += __shfl_xor_sync(~0u, q1, 1); q1 += __shfl_xor_sync(~0u, q1, 2);
        float r0s = rsqrtf(q0 * (1.f / H) + EPS), r1s = rsqrtf(q1 * (1.f / H) + EPS);
#pragma unroll
        for (int t = 0; t < 16; t++) {
            int col = t * 8 + bq;
            float2 gg = *(float2*)&sB[640 + col];
            float2 bb = *(float2*)&sB[768 + col];
            float h0 = (x[t][0] - m0) * r0s * gg.x + bb.x;
            float h1 = (x[t][1] - m0) * r0s * gg.y + bb.y;
            float h2 = (x[t][2] - m1) * r1s * gg.x + bb.x;
            float h3 = (x[t][3] - m1) * r1s * gg.y + bb.y;
            uint32_t hi0, lo0, hi1, lo1;
            split_pack(h0, h1, hi0, lo0);
            split_pack(h2, h3, hi1, lo1);
            uint32_t o0 = (uint32_t)(r0 * SB_STRIDE + col) * 2;
            uint32_t o1 = (uint32_t)((r0 + 8) * SB_STRIDE + col) * 2;
            *(uint32_t*)(sm + OFF_A1HI + o0) = hi0;
            *(uint32_t*)(sm + OFF_A1LO + o0) = lo0;
            *(uint32_t*)(sm + OFF_A1HI + o1) = hi1;
            *(uint32_t*)(sm + OFF_A1LO + o1) = lo1;
        }
    }
    CP_WAIT0();
    __syncthreads();

    float acc2[16][4];
#pragma unroll
    for (int t = 0; t < 16; t++)
        { acc2[t][0] = 0.f; acc2[t][1] = 0.f; acc2[t][2] = 0.f; acc2[t][3] = 0.f; }

    uint32_t aH[8][4], aL[8][4];

#define NCOMPUTE1(half, s) do { \
    uint32_t _sBhi = sb + OFF_NB + ((s) & 1) * CHUNK_BYTES; \
    uint32_t _sBlo = _sBhi + CHUNK_HALF; \
    _Pragma("unroll") for (int js = 0; js < 4; js++) { \
        uint32_t fAh[4], fAl[4]; \
        uint32_t _acol = (uint32_t)((half) * 64 + js * 16) * 2; \
        ldsm_x4(fAh, sb + OFF_A1HI + a_row_off + _acol); \
        ldsm_x4(fAl, sb + OFF_A1LO + a_row_off + _acol); \
        KSTEP_G(acc1, fAh, fAl, _sBhi, _sBlo, (uint32_t)(js * 16 * SB_STRIDE) * 2); \
    } } while (0)

#define NCOMPUTE2(JB, s) do { \
    uint32_t _sBhi = sb + OFF_NB + ((s) & 1) * CHUNK_BYTES; \
    uint32_t _sBlo = _sBhi + CHUNK_HALF; \
    _Pragma("unroll") for (int js = 0; js < 4; js++) { \
        KSTEP_G(acc2, aH[(JB) + js], aL[(JB) + js], _sBhi, _sBlo, (uint32_t)(js * 16 * SB_STRIDE) * 2); \
    } } while (0)

#pragma unroll 1
    for (int c = 0; c < 4; c++) {
        const int s0u = 4 * c;
        float acc1[16][4];
#pragma unroll
        for (int t = 0; t < 16; t++)
            { acc1[t][0] = 0.f; acc1[t][1] = 0.f; acc1[t][2] = 0.f; acc1[t][3] = 0.f; }

        PREFETCH_N(s0u + 1); NCOMPUTE1(0, s0u);     CP_WAIT0(); __syncthreads();
        PREFETCH_N(s0u + 2); NCOMPUTE1(1, s0u + 1); CP_WAIT0(); __syncthreads();

        // bias + relu + repack acc1 -> GEMM2 A fragments
#pragma unroll
        for (int t = 0; t < 16; t++) {
            float2 bb = *(float2*)&sB[c * 128 + t * 8 + bq];
            float v0 = fmaxf(acc1[t][0] + bb.x, 0.f);
            float v1 = fmaxf(acc1[t][1] + bb.y, 0.f);
            float v2 = fmaxf(acc1[t][2] + bb.x, 0.f);
            float v3 = fmaxf(acc1[t][3] + bb.y, 0.f);
            uint32_t h01, l01, h23, l23;
            split_pack(v0, v1, h01, l01);
            split_pack(v2, v3, h23, l23);
            int _j = t >> 1, _b = (t & 1) * 2;
            aH[_j][_b] = h01; aH[_j][_b + 1] = h23;
            aL[_j][_b] = l01; aL[_j][_b + 1] = l23;
        }

        PREFETCH_N(s0u + 3); NCOMPUTE2(0, s0u + 2); CP_WAIT0(); __syncthreads();
        if (c < 3) {
            PREFETCH_N(s0u + 4); NCOMPUTE2(4, s0u + 3); CP_WAIT0(); __syncthreads();
        } else {
            NCOMPUTE2(4, s0u + 3); __syncthreads();
        }
    }

    // ---- residual + LN2 + store (fragment registers) ----
    {
        float y[16][4];
#pragma unroll
        for (int t = 0; t < 16; t++) {
            int col = t * 8 + bq;
            float2 d2 = *(float2*)&sB[512 + col];
            uint32_t o0 = (uint32_t)(r0 * SB_STRIDE + col) * 2;
            uint32_t o1 = (uint32_t)((r0 + 8) * SB_STRIDE + col) * 2;
            uint32_t hi0 = *(uint32_t*)(sm + OFF_A1HI + o0);
            uint32_t lo0 = *(uint32_t*)(sm + OFF_A1LO + o0);
            uint32_t hi1 = *(uint32_t*)(sm + OFF_A1HI + o1);
            uint32_t lo1 = *(uint32_t*)(sm + OFF_A1LO + o1);
            float h0 = __uint_as_float(hi0 << 16) + __uint_as_float(lo0 << 16);
            float h1 = __uint_as_float(hi0 & 0xffff0000u) + __uint_as_float(lo0 & 0xffff0000u);
            float h2 = __uint_as_float(hi1 << 16) + __uint_as_float(lo1 << 16);
            float h3 = __uint_as_float(hi1 & 0xffff0000u) + __uint_as_float(lo1 & 0xffff0000u);
            y[t][0] = h0 + acc2[t][0] + d2.x;
            y[t][1] = h1 + acc2[t][1] + d2.y;
            y[t][2] = h2 + acc2[t][2] + d2.x;
            y[t][3] = h3 + acc2[t][3] + d2.y;
        }
        float s0 = 0.f, s1 = 0.f;
#pragma unroll
        for (int t = 0; t < 16; t++) { s0 += y[t][0] + y[t][1]; s1 += y[t][2] + y[t][3]; }
        s0 += __shfl_xor_sync(~0u, s0, 1); s0 += __shfl_xor_sync(~0u, s0, 2);
        s1 += __shfl_xor_sync(~0u, s1, 1); s1 += __shfl_xor_sync(~0u, s1, 2);
        float m0 = s0 * (1.f / H), m1 = s1 * (1.f / H);
        float q0 = 0.f, q1 = 0.f;
#pragma unroll
        for (int t = 0; t < 16; t++) {
            float d0 = y[t][0] - m0, d1 = y[t][1] - m0;
            float d2 = y[t][2] - m1, d3 = y[t][3] - m1;
            q0 += d0 * d0 + d1 * d1; q1 += d2 * d2 + d3 * d3;
        }
        q0 += __shfl_xor_sync(~0u, q0, 1); q0 += __shfl_xor_sync(~0u, q0, 2);
        q1 += __shfl_xor_sync(~0u, q1, 1); q1 += __shfl_xor_sync(~0u, q1, 2);
        float r0s = rsqrtf(q0 * (1.f / H) + EPS), r1s = rsqrtf(q1 * (1.f / H) + EPS);
#pragma unroll
        for (int t = 0; t < 16; t++) {
            int col = t * 8 + bq;
            float2 gg = *(float2*)&sB[896 + col];
            float2 bb = *(float2*)&sB[1024 + col];
            if (ok0) {
                float2 o;
                o.x = (y[t][0] - m0) * r0s * gg.x + bb.x;
                o.y = (y[t][1] - m0) * r0s * gg.y + bb.y;
                *(float2*)(out + gr0 * H + col) = o;
            }
            if (ok1) {
                float2 o;
                o.x = (y[t][2] - m1) * r1s * gg.x + bb.x;
                o.y = (y[t][3] - m1) * r1s * gg.y + bb.y;
                *(float2*)(out + gr1 * H + col) = o;
            }
        }
    }
#undef PREFETCH_N
#undef NCOMPUTE1
#undef NCOMPUTE2
}

// ===========================================================================
extern "C" void kernel_launch(void* const* d_in, const int* in_sizes, int n_in,
                              void* d_out, int out_size) {
    const float* h_V  = (const float*)d_in[0];
    const float* h_E  = (const float*)d_in[1];
    const void*  eidx = (const void*)d_in[2];
    const float* W1 = (const float*)d_in[3];
    const float* b1 = (const float*)d_in[4];
    const float* W2 = (const float*)d_in[5];
    const float* b2 = (const float*)d_in[6];
    const float* W3 = (const float*)d_in[7];
    const float* b3 = (const float*)d_in[8];
    const float* D1 = (const float*)d_in[9];
    const float* db1 = (const float*)d_in[10];
    const float* D2 = (const float*)d_in[11];
    const float* db2 = (const float*)d_in[12];
    const float* g1 = (const float*)d_in[13];
    const float* be1 = (const float*)d_in[14];
    const float* g2 = (const float*)d_in[15];
    const float* be2 = (const float*)d_in[16];
    float* out = (float*)d_out;

    cudaFuncSetAttribute(edge_mma_kernel, cudaFuncAttributeMaxDynamicSharedMemorySize, EDGE_SMEM);
    cudaFuncSetAttribute(node_mma_kernel, cudaFuncAttributeMaxDynamicSharedMemorySize, NODE_SMEM);

    void* dh_ptr = nullptr;
    cudaGetSymbolAddress(&dh_ptr, g_dh);
    cudaMemsetAsync(dh_ptr, 0, sizeof(float) * (size_t)N_NODES * H, 0);

    detect_idx_kernel<<<1, 1>>>(eidx);
    prep_weights_kernel<<<768, 256>>>(W1, W2, W3, D1, D2);
    edge_mma_kernel<<<N_EDGES / M_TILE, 256, EDGE_SMEM>>>(h_E, eidx, b1, b2, b3);
    node_mma_kernel<<<(N_NODES + 127) / 128, 256, NODE_SMEM>>>(
        h_V, db1, db2, g1, be1, g2, be2, out);
}

// round 6
// speedup vs baseline: 4.9755x; 1.1065x over previous
#include <cuda_runtime.h>
#include <cuda_bf16.h>
#include <cuda_fp16.h>
#include <cstdint>

#define N_NODES 100000
#define N_EDGES 800000
#define H 128
#define HE 256
#define EPS 1e-5f

// ---------------- edge kernel geometry ----------------
#define M_TILE 128
#define SA_STRIDE 264       // padded elems per A row (528B ≡ 16 mod 128)
#define SB_STRIDE 136       // padded elems per B row (272B ≡ 16 mod 128)
#define ECHUNK 17408        // edge B chunk: 64 rows * 136 * 2B (fp16, hi only)
#define CHUNK_HALF 17408    // node layout half
#define CHUNK_BYTES 34816   // node chunk (hi + lo bf16)
#define OFF_AHI  1536
#define OFF_ALO  (1536 + 67584)
#define OFF_SB   (69120 + 67584)            // 136704
#define EDGE_SMEM (136704 + 2 * ECHUNK)     // 171520

// ---------------- node kernel geometry ----------------
#define OFF_A1HI  4608
#define OFF_A1LO  (4608 + 34816)
#define OFF_NB    (4608 + 69632)          // 74240
#define NODE_SMEM (OFF_NB + 2 * 34816)    // 143872

// ---------------- globals ----------------
__device__ float g_dh[(size_t)N_NODES * H];
__device__ int g_idx_is64;
// edge weights: 8 chunks of fp16 (hi only)
__device__ __align__(1024) unsigned char g_Bh16[8 * ECHUNK];
// node weights (bf16 hi/lo), stream order units 0..15:
// for c in 0..3: D1[k0-63, n128c..], D1[k64-127,...], D2[k128c+0-63], D2[k128c+64-127]
__device__ __align__(1024) unsigned char g_B[16 * CHUNK_BYTES];

// ===========================================================================
// PTX helpers (baseline ISA only)
// ===========================================================================
__device__ __forceinline__ uint32_t smem_u32(const void* p) {
    uint32_t a;
    asm("{ .reg .u64 t; cvta.to.shared.u64 t, %1; cvt.u32.u64 %0, t; }" : "=r"(a) : "l"(p));
    return a;
}
__device__ __forceinline__ void ldsm_x4(uint32_t* r, uint32_t addr) {
    asm volatile("ldmatrix.sync.aligned.m8n8.x4.shared.b16 {%0,%1,%2,%3}, [%4];"
                 : "=r"(r[0]), "=r"(r[1]), "=r"(r[2]), "=r"(r[3]) : "r"(addr));
}
__device__ __forceinline__ void ldsm_x4_t(uint32_t* r, uint32_t addr) {
    asm volatile("ldmatrix.sync.aligned.m8n8.x4.trans.shared.b16 {%0,%1,%2,%3}, [%4];"
                 : "=r"(r[0]), "=r"(r[1]), "=r"(r[2]), "=r"(r[3]) : "r"(addr));
}
// bf16 mma (node kernel)
__device__ __forceinline__ void mma16816(float* d, const uint32_t* a, uint32_t b0, uint32_t b1) {
    asm volatile("mma.sync.aligned.m16n8k16.row.col.f32.bf16.bf16.f32 "
                 "{%0,%1,%2,%3}, {%4,%5,%6,%7}, {%8,%9}, {%0,%1,%2,%3};"
                 : "+f"(d[0]), "+f"(d[1]), "+f"(d[2]), "+f"(d[3])
                 : "r"(a[0]), "r"(a[1]), "r"(a[2]), "r"(a[3]), "r"(b0), "r"(b1));
}
// fp16 mma (edge kernel)
__device__ __forceinline__ void mma16816h(float* d, const uint32_t* a, uint32_t b0, uint32_t b1) {
    asm volatile("mma.sync.aligned.m16n8k16.row.col.f32.f16.f16.f32 "
                 "{%0,%1,%2,%3}, {%4,%5,%6,%7}, {%8,%9}, {%0,%1,%2,%3};"
                 : "+f"(d[0]), "+f"(d[1]), "+f"(d[2]), "+f"(d[3])
                 : "r"(a[0]), "r"(a[1]), "r"(a[2]), "r"(a[3]), "r"(b0), "r"(b1));
}
__device__ __forceinline__ void cp_async16(uint32_t saddr, const void* g) {
    asm volatile("cp.async.cg.shared.global [%0], [%1], 16;" :: "r"(saddr), "l"(g));
}
#define CP_COMMIT() asm volatile("cp.async.commit_group;")
#define CP_WAIT0()  asm volatile("cp.async.wait_group 0;" ::: "memory")

// bf16 split (node)
__device__ __forceinline__ void split_pack(float v0, float v1, uint32_t& hi, uint32_t& lo) {
    uint32_t u0 = __float_as_uint(v0), u1 = __float_as_uint(v1);
    hi = (u0 >> 16) | (u1 & 0xffff0000u);
    float f0 = __uint_as_float(u0 & 0xffff0000u);
    float f1 = __uint_as_float(u1 & 0xffff0000u);
    lo = (uint32_t)__bfloat16_as_ushort(__float2bfloat16(v0 - f0)) |
         ((uint32_t)__bfloat16_as_ushort(__float2bfloat16(v1 - f1)) << 16);
}
// fp16 split (edge activations, 22-bit effective)
__device__ __forceinline__ void split_pack_h(float v0, float v1, uint32_t& hi, uint32_t& lo) {
    __half h0 = __float2half_rn(v0), h1 = __float2half_rn(v1);
    hi = (uint32_t)__half_as_ushort(h0) | ((uint32_t)__half_as_ushort(h1) << 16);
    float r0 = v0 - __half2float(h0), r1 = v1 - __half2float(h1);
    lo = (uint32_t)__half_as_ushort(__float2half_rn(r0)) |
         ((uint32_t)__half_as_ushort(__float2half_rn(r1)) << 16);
}

// 3-term bf16 k16 step (node kernel)
#define KSTEP_G(ACC, fAh, fAl, sBhi, sBlo, brow) do { \
    _Pragma("unroll") for (int p = 0; p < 8; p++) { \
        uint32_t bh[4], bl[4]; \
        uint32_t _bo = b_frag_off + (brow) + (uint32_t)(p * 16) * 2; \
        ldsm_x4_t(bh, (sBhi) + _bo); \
        ldsm_x4_t(bl, (sBlo) + _bo); \
        mma16816((ACC)[2 * p],     fAh, bh[0], bh[1]); \
        mma16816((ACC)[2 * p],     fAh, bl[0], bl[1]); \
        mma16816((ACC)[2 * p],     fAl, bh[0], bh[1]); \
        mma16816((ACC)[2 * p + 1], fAh, bh[2], bh[3]); \
        mma16816((ACC)[2 * p + 1], fAh, bl[2], bl[3]); \
        mma16816((ACC)[2 * p + 1], fAl, bh[2], bh[3]); \
    } } while (0)

// 2-term fp16 k16 step (edge kernel): (aH+aL) x bH
#define KSTEP_E(ACC, fAh, fAl, sBhi, brow) do { \
    _Pragma("unroll") for (int p = 0; p < 8; p++) { \
        uint32_t bh[4]; \
        uint32_t _bo = b_frag_off + (brow) + (uint32_t)(p * 16) * 2; \
        ldsm_x4_t(bh, (sBhi) + _bo); \
        mma16816h((ACC)[2 * p],     fAh, bh[0], bh[1]); \
        mma16816h((ACC)[2 * p],     fAl, bh[0], bh[1]); \
        mma16816h((ACC)[2 * p + 1], fAh, bh[2], bh[3]); \
        mma16816h((ACC)[2 * p + 1], fAl, bh[2], bh[3]); \
    } } while (0)

// ---------------------------------------------------------------------------
__global__ void detect_idx_kernel(const void* eidx) {
    const long long* p = (const long long*)eidx;
    int is64 = 1;
    for (int i = 0; i < 64; i++) {
        long long v = p[i];
        if (v < 0 || v >= N_NODES) { is64 = 0; break; }
    }
    g_idx_is64 = is64;
}

// ---------------------------------------------------------------------------
// Weight prep: edge W1/W2/W3 -> fp16 chunks; node D1/D2 -> bf16 hi/lo units
// ---------------------------------------------------------------------------
__global__ void prep_weights_kernel(const float* __restrict__ W1,
                                    const float* __restrict__ W2,
                                    const float* __restrict__ W3,
                                    const float* __restrict__ D1,
                                    const float* __restrict__ D2) {
    int idx = blockIdx.x * 256 + threadIdx.x;    // 0 .. 196607
    if (idx < 65536) {
        int n = idx & 127;
        int krow = idx >> 7;
        const float* W; int k, unit;
        if (krow < 256)      { W = W1; k = krow;       unit = krow >> 6; }
        else if (krow < 384) { W = W2; k = krow - 256; unit = 4 + ((krow - 256) >> 6); }
        else                 { W = W3; k = krow - 384; unit = 6 + ((krow - 384) >> 6); }
        float v = W[(size_t)k * 128 + n];
        int kk = k & 63;
        *(unsigned short*)(g_Bh16 + (size_t)unit * ECHUNK + (size_t)(kk * SB_STRIDE + n) * 2) =
            __half_as_ushort(__float2half_rn(v));
        return;
    }
    float v; int unit, kk, n;
    if (idx < 131072) {
        int i = idx - 65536;                     // D1: 128 x 512
        int k = i >> 9, n512 = i & 511;
        int c = n512 >> 7; n = n512 & 127;
        int half = k >> 6; kk = k & 63;
        unit = 4 * c + half;
        v = D1[(size_t)k * 512 + n512];
    } else {
        int i = idx - 131072;                    // D2: 512 x 128
        int k = i >> 7; n = i & 127;
        int c = k >> 7, krem = k & 127;
        int half = krem >> 6; kk = krem & 63;
        unit = 4 * c + 2 + half;
        v = D2[(size_t)k * 128 + n];
    }
    size_t off = (size_t)unit * CHUNK_BYTES + (size_t)(kk * SB_STRIDE + n) * 2;
    uint32_t u = __float_as_uint(v);
    *(unsigned short*)(g_B + off) = (unsigned short)(u >> 16);
    float fhi = __uint_as_float(u & 0xffff0000u);
    *(unsigned short*)(g_B + off + CHUNK_HALF) = __bfloat16_as_ushort(__float2bfloat16(v - fhi));
}

// ===========================================================================
// Edge kernel: 2-term fp16 HMMA 3-layer MLP + scatter
// ===========================================================================
__global__ __launch_bounds__(256, 1)
void edge_mma_kernel(const float* __restrict__ hE, const void* __restrict__ eidx,
                     const float* __restrict__ b1, const float* __restrict__ b2,
                     const float* __restrict__ b3) {
    extern __shared__ char sm[];
    const uint32_t sb = smem_u32(sm);
    const int tid = threadIdx.x, wid = tid >> 5, lane = tid & 31;
    const long long ebase = (long long)blockIdx.x * M_TILE;

    if (tid < 128) {
        ((float*)sm)[tid] = b1[tid];
        ((float*)sm)[128 + tid] = b2[tid];
        ((float*)sm)[256 + tid] = b3[tid];
    }

    for (int i = tid; i < 1088; i += 256)
        cp_async16(sb + OFF_SB + i * 16, g_Bh16 + i * 16);
    CP_COMMIT();

    // stage layer-1 A: h_E [128 x 256] f32 -> fp16 hi/lo, padded stride
    {
        const float4* gE = (const float4*)(hE + ebase * HE);
        char* aHi = sm + OFF_AHI;
        char* aLo = sm + OFF_ALO;
        for (int i = tid; i < 128 * 64; i += 256) {
            int row = i >> 6, c4 = i & 63;
            float4 v = gE[i];
            uint32_t h01, l01, h23, l23;
            split_pack_h(v.x, v.y, h01, l01);
            split_pack_h(v.z, v.w, h23, l23);
            uint32_t off = (uint32_t)(row * SA_STRIDE + c4 * 4) * 2;
            *(uint2*)(aHi + off) = make_uint2(h01, h23);
            *(uint2*)(aLo + off) = make_uint2(l01, l23);
        }
    }
    CP_WAIT0();
    __syncthreads();

    const int mrow = lane & 7, mid = lane >> 3;
    const uint32_t a_row_off =
        (uint32_t)((wid * 16 + (mid & 1) * 8 + mrow) * SA_STRIDE + (mid >> 1) * 8) * 2;
    const uint32_t b_frag_off =
        (uint32_t)(((mid & 1) * 8 + mrow) * SB_STRIDE + (mid >> 1) * 8) * 2;
    const int bq = 2 * (lane & 3);

    float acc[16][4];
    uint32_t aH[8][4], aL[8][4];
    float* sBias = (float*)sm;

#define ZERO_ACC() do { \
    _Pragma("unroll") for (int t = 0; t < 16; t++) \
        { acc[t][0] = 0.f; acc[t][1] = 0.f; acc[t][2] = 0.f; acc[t][3] = 0.f; } } while (0)

#define PREFETCH(c) do { \
    const unsigned char* _src = g_Bh16 + (c) * ECHUNK; \
    uint32_t _dst = sb + OFF_SB + ((c) & 1) * ECHUNK; \
    for (int i = tid; i < 1088; i += 256) cp_async16(_dst + i * 16, _src + i * 16); \
    CP_COMMIT(); } while (0)

#define COMPUTE_SMEM(c) do { \
    uint32_t _sBhi = sb + OFF_SB + ((c) & 1) * ECHUNK; \
    _Pragma("unroll") for (int js = 0; js < 4; js++) { \
        uint32_t fAh[4], fAl[4]; \
        uint32_t _acol = (uint32_t)((c) * 64 + js * 16) * 2; \
        ldsm_x4(fAh, sb + OFF_AHI + a_row_off + _acol); \
        ldsm_x4(fAl, sb + OFF_ALO + a_row_off + _acol); \
        KSTEP_E(acc, fAh, fAl, _sBhi, (uint32_t)(js * 16 * SB_STRIDE) * 2); \
    } } while (0)

#define COMPUTE_REG(JB, c) do { \
    uint32_t _sBhi = sb + OFF_SB + ((c) & 1) * ECHUNK; \
    _Pragma("unroll") for (int js = 0; js < 4; js++) { \
        KSTEP_E(acc, aH[(JB) + js], aL[(JB) + js], _sBhi, (uint32_t)(js * 16 * SB_STRIDE) * 2); \
    } } while (0)

#define EPILOGUE_RELU(biasBase) do { \
    _Pragma("unroll") for (int t = 0; t < 16; t++) { \
        float2 bb = *(float2*)&sBias[(biasBase) + t * 8 + bq]; \
        float v0 = fmaxf(acc[t][0] + bb.x, 0.f); \
        float v1 = fmaxf(acc[t][1] + bb.y, 0.f); \
        float v2 = fmaxf(acc[t][2] + bb.x, 0.f); \
        float v3 = fmaxf(acc[t][3] + bb.y, 0.f); \
        uint32_t h01, l01, h23, l23; \
        split_pack_h(v0, v1, h01, l01); \
        split_pack_h(v2, v3, h23, l23); \
        int _j = t >> 1, _b = (t & 1) * 2; \
        aH[_j][_b] = h01; aH[_j][_b + 1] = h23; \
        aL[_j][_b] = l01; aL[_j][_b + 1] = l23; \
    } } while (0)

    ZERO_ACC();
    PREFETCH(1); COMPUTE_SMEM(0); CP_WAIT0(); __syncthreads();
    PREFETCH(2); COMPUTE_SMEM(1); CP_WAIT0(); __syncthreads();
    PREFETCH(3); COMPUTE_SMEM(2); CP_WAIT0(); __syncthreads();
    PREFETCH(4); COMPUTE_SMEM(3); CP_WAIT0(); __syncthreads();
    EPILOGUE_RELU(0); ZERO_ACC();
    PREFETCH(5); COMPUTE_REG(0, 4); CP_WAIT0(); __syncthreads();
    PREFETCH(6); COMPUTE_REG(4, 5); CP_WAIT0(); __syncthreads();
    EPILOGUE_RELU(128); ZERO_ACC();
    PREFETCH(7); COMPUTE_REG(0, 6); CP_WAIT0(); __syncthreads();
    COMPUTE_REG(4, 7); __syncthreads();

    {
        float* sOut = (float*)(sm + OFF_AHI);
        int row0 = wid * 16 + (lane >> 2);
#pragma unroll
        for (int t = 0; t < 16; t++) {
            float2 bb = *(float2*)&sBias[256 + t * 8 + bq];
            float v0 = acc[t][0] + bb.x, v1 = acc[t][1] + bb.y;
            float v2 = acc[t][2] + bb.x, v3 = acc[t][3] + bb.y;
            *(float2*)&sOut[row0 * 132 + t * 8 + bq] = make_float2(v0, v1);
            *(float2*)&sOut[(row0 + 8) * 132 + t * 8 + bq] = make_float2(v2, v3);
        }
        __syncthreads();

        const int is64 = g_idx_is64;
        for (int e = wid; e < 128; e += 8) {
            long long s = is64 ? ((const long long*)eidx)[ebase + e]
                               : (long long)((const int*)eidx)[ebase + e];
            float* dst = g_dh + (size_t)s * H;
            const float* srow = sOut + e * 132;
#pragma unroll
            for (int q = 0; q < 4; q++) {
                int col = lane + q * 32;
                atomicAdd(dst + col, srow[col]);
            }
        }
    }
#undef ZERO_ACC
#undef PREFETCH
#undef COMPUTE_SMEM
#undef COMPUTE_REG
#undef EPILOGUE_RELU
}

// ===========================================================================
// Node kernel: split-bf16 HMMA FFN (unchanged from passing R5)
// ===========================================================================
__global__ __launch_bounds__(256, 1)
void node_mma_kernel(const float* __restrict__ hV,
                     const float* __restrict__ db1, const float* __restrict__ db2,
                     const float* __restrict__ g1, const float* __restrict__ be1,
                     const float* __restrict__ g2, const float* __restrict__ be2,
                     float* __restrict__ out) {
    extern __shared__ char sm[];
    const uint32_t sb = smem_u32(sm);
    const int tid = threadIdx.x, wid = tid >> 5, lane = tid & 31;
    const long long nbase = (long long)blockIdx.x * 128;

    float* sB = (float*)sm;
    for (int i = tid; i < 512; i += 256) sB[i] = db1[i];
    if (tid < 128) {
        sB[512 + tid] = db2[tid];
        sB[640 + tid] = g1[tid];  sB[768 + tid] = be1[tid];
        sB[896 + tid] = g2[tid];  sB[1024 + tid] = be2[tid];
    }

#define PREFETCH_N(s) do { \
    const unsigned char* _src = g_B + (s) * CHUNK_BYTES; \
    uint32_t _dst = sb + OFF_NB + ((s) & 1) * CHUNK_BYTES; \
    for (int i = tid; i < 2176; i += 256) cp_async16(_dst + i * 16, _src + i * 16); \
    CP_COMMIT(); } while (0)

    PREFETCH_N(0);

    const int mrow = lane & 7, mid = lane >> 3;
    const uint32_t a_row_off =
        (uint32_t)((wid * 16 + (mid & 1) * 8 + mrow) * SB_STRIDE + (mid >> 1) * 8) * 2;
    const uint32_t b_frag_off =
        (uint32_t)(((mid & 1) * 8 + mrow) * SB_STRIDE + (mid >> 1) * 8) * 2;
    const int bq = 2 * (lane & 3);
    const int r0 = wid * 16 + (lane >> 2);
    const long long gr0 = nbase + r0, gr1 = gr0 + 8;
    const bool ok0 = gr0 < N_NODES, ok1 = gr1 < N_NODES;

    {
        float x[16][4];
#pragma unroll
        for (int t = 0; t < 16; t++) {
            int col = t * 8 + bq;
            if (ok0) {
                float2 v = *(const float2*)(hV + gr0 * H + col);
                float2 d = *(const float2*)(g_dh + gr0 * H + col);
                x[t][0] = v.x + d.x * (1.f / 30.f);
                x[t][1] = v.y + d.y * (1.f / 30.f);
            } else { x[t][0] = 0.f; x[t][1] = 0.f; }
            if (ok1) {
                float2 v = *(const float2*)(hV + gr1 * H + col);
                float2 d = *(const float2*)(g_dh + gr1 * H + col);
                x[t][2] = v.x + d.x * (1.f / 30.f);
                x[t][3] = v.y + d.y * (1.f / 30.f);
            } else { x[t][2] = 0.f; x[t][3] = 0.f; }
        }
        float s0 = 0.f, s1 = 0.f;
#pragma unroll
        for (int t = 0; t < 16; t++) { s0 += x[t][0] + x[t][1]; s1 += x[t][2] + x[t][3]; }
        s0 += __shfl_xor_sync(~0u, s0, 1); s0 += __shfl_xor_sync(~0u, s0, 2);
        s1 += __shfl_xor_sync(~0u, s1, 1); s1 += __shfl_xor_sync(~0u, s1, 2);
        float m0 = s0 * (1.f / H), m1 = s1 * (1.f / H);
        float q0 = 0.f, q1 = 0.f;
#pragma unroll
        for (int t = 0; t < 16; t++) {
            float d0 = x[t][0] - m0, d1 = x[t][1] - m0;
            float d2 = x[t][2] - m1, d3 = x[t][3] - m1;
            q0 += d0 * d0 + d1 * d1; q1 += d2 * d2 + d3 * d3;
        }
        q0 += __shfl_xor_sync(~0u, q0, 1); q0 += __shfl_xor_sync(~0u, q0, 2);
        q1 += __shfl_xor_sync(~0u, q1, 1); q1 += __shfl_xor_sync(~0u, q1, 2);
        float r0s = rsqrtf(q0 * (1.f / H) + EPS), r1s = rsqrtf(q1 * (1.f / H) + EPS);
#pragma unroll
        for (int t = 0; t < 16; t++) {
            int col = t * 8 + bq;
            float2 gg = *(float2*)&sB[640 + col];
            float2 bb = *(float2*)&sB[768 + col];
            float h0 = (x[t][0] - m0) * r0s * gg.x + bb.x;
            float h1 = (x[t][1] - m0) * r0s * gg.y + bb.y;
            float h2 = (x[t][2] - m1) * r1s * gg.x + bb.x;
            float h3 = (x[t][3] - m1) * r1s * gg.y + bb.y;
            uint32_t hi0, lo0, hi1, lo1;
            split_pack(h0, h1, hi0, lo0);
            split_pack(h2, h3, hi1, lo1);
            uint32_t o0 = (uint32_t)(r0 * SB_STRIDE + col) * 2;
            uint32_t o1 = (uint32_t)((r0 + 8) * SB_STRIDE + col) * 2;
            *(uint32_t*)(sm + OFF_A1HI + o0) = hi0;
            *(uint32_t*)(sm + OFF_A1LO + o0) = lo0;
            *(uint32_t*)(sm + OFF_A1HI + o1) = hi1;
            *(uint32_t*)(sm + OFF_A1LO + o1) = lo1;
        }
    }
    CP_WAIT0();
    __syncthreads();

    float acc2[16][4];
#pragma unroll
    for (int t = 0; t < 16; t++)
        { acc2[t][0] = 0.f; acc2[t][1] = 0.f; acc2[t][2] = 0.f; acc2[t][3] = 0.f; }

    uint32_t aH[8][4], aL[8][4];

#define NCOMPUTE1(half, s) do { \
    uint32_t _sBhi = sb + OFF_NB + ((s) & 1) * CHUNK_BYTES; \
    uint32_t _sBlo = _sBhi + CHUNK_HALF; \
    _Pragma("unroll") for (int js = 0; js < 4; js++) { \
        uint32_t fAh[4], fAl[4]; \
        uint32_t _acol = (uint32_t)((half) * 64 + js * 16) * 2; \
        ldsm_x4(fAh, sb + OFF_A1HI + a_row_off + _acol); \
        ldsm_x4(fAl, sb + OFF_A1LO + a_row_off + _acol); \
        KSTEP_G(acc1, fAh, fAl, _sBhi, _sBlo, (uint32_t)(js * 16 * SB_STRIDE) * 2); \
    } } while (0)

#define NCOMPUTE2(JB, s) do { \
    uint32_t _sBhi = sb + OFF_NB + ((s) & 1) * CHUNK_BYTES; \
    uint32_t _sBlo = _sBhi + CHUNK_HALF; \
    _Pragma("unroll") for (int js = 0; js < 4; js++) { \
        KSTEP_G(acc2, aH[(JB) + js], aL[(JB) + js], _sBhi, _sBlo, (uint32_t)(js * 16 * SB_STRIDE) * 2); \
    } } while (0)

#pragma unroll 1
    for (int c = 0; c < 4; c++) {
        const int s0u = 4 * c;
        float acc1[16][4];
#pragma unroll
        for (int t = 0; t < 16; t++)
            { acc1[t][0] = 0.f; acc1[t][1] = 0.f; acc1[t][2] = 0.f; acc1[t][3] = 0.f; }

        PREFETCH_N(s0u + 1); NCOMPUTE1(0, s0u);     CP_WAIT0(); __syncthreads();
        PREFETCH_N(s0u + 2); NCOMPUTE1(1, s0u + 1); CP_WAIT0(); __syncthreads();

#pragma unroll
        for (int t = 0; t < 16; t++) {
            float2 bb = *(float2*)&sB[c * 128 + t * 8 + bq];
            float v0 = fmaxf(acc1[t][0] + bb.x, 0.f);
            float v1 = fmaxf(acc1[t][1] + bb.y, 0.f);
            float v2 = fmaxf(acc1[t][2] + bb.x, 0.f);
            float v3 = fmaxf(acc1[t][3] + bb.y, 0.f);
            uint32_t h01, l01, h23, l23;
            split_pack(v0, v1, h01, l01);
            split_pack(v2, v3, h23, l23);
            int _j = t >> 1, _b = (t & 1) * 2;
            aH[_j][_b] = h01; aH[_j][_b + 1] = h23;
            aL[_j][_b] = l01; aL[_j][_b + 1] = l23;
        }

        PREFETCH_N(s0u + 3); NCOMPUTE2(0, s0u + 2); CP_WAIT0(); __syncthreads();
        if (c < 3) {
            PREFETCH_N(s0u + 4); NCOMPUTE2(4, s0u + 3); CP_WAIT0(); __syncthreads();
        } else {
            NCOMPUTE2(4, s0u + 3); __syncthreads();
        }
    }

    {
        float y[16][4];
#pragma unroll
        for (int t = 0; t < 16; t++) {
            int col = t * 8 + bq;
            float2 d2 = *(float2*)&sB[512 + col];
            uint32_t o0 = (uint32_t)(r0 * SB_STRIDE + col) * 2;
            uint32_t o1 = (uint32_t)((r0 + 8) * SB_STRIDE + col) * 2;
            uint32_t hi0 = *(uint32_t*)(sm + OFF_A1HI + o0);
            uint32_t lo0 = *(uint32_t*)(sm + OFF_A1LO + o0);
            uint32_t hi1 = *(uint32_t*)(sm + OFF_A1HI + o1);
            uint32_t lo1 = *(uint32_t*)(sm + OFF_A1LO + o1);
            float h0 = __uint_as_float(hi0 << 16) + __uint_as_float(lo0 << 16);
            float h1 = __uint_as_float(hi0 & 0xffff0000u) + __uint_as_float(lo0 & 0xffff0000u);
            float h2 = __uint_as_float(hi1 << 16) + __uint_as_float(lo1 << 16);
            float h3 = __uint_as_float(hi1 & 0xffff0000u) + __uint_as_float(lo1 & 0xffff0000u);
            y[t][0] = h0 + acc2[t][0] + d2.x;
            y[t][1] = h1 + acc2[t][1] + d2.y;
            y[t][2] = h2 + acc2[t][2] + d2.x;
            y[t][3] = h3 + acc2[t][3] + d2.y;
        }
        float s0 = 0.f, s1 = 0.f;
#pragma unroll
        for (int t = 0; t < 16; t++) { s0 += y[t][0] + y[t][1]; s1 += y[t][2] + y[t][3]; }
        s0 += __shfl_xor_sync(~0u, s0, 1); s0 += __shfl_xor_sync(~0u, s0, 2);
        s1 += __shfl_xor_sync(~0u, s1, 1); s1 += __shfl_xor_sync(~0u, s1, 2);
        float m0 = s0 * (1.f / H), m1 = s1 * (1.f / H);
        float q0 = 0.f, q1 = 0.f;
#pragma unroll
        for (int t = 0; t < 16; t++) {
            float d0 = y[t][0] - m0, d1 = y[t][1] - m0;
            float d2 = y[t][2] - m1, d3 = y[t][3] - m1;
            q0 += d0 * d0 + d1 * d1; q1 += d2 * d2 + d3 * d3;
        }
        q0 += __shfl_xor_sync(~0u, q0, 1); q0 += __shfl_xor_sync(~0u, q0, 2);
        q1 += __shfl_xor_sync(~0u, q1, 1); q1 += __shfl_xor_sync(~0u, q1, 2);
        float r0s = rsqrtf(q0 * (1.f / H) + EPS), r1s = rsqrtf(q1 * (1.f / H) + EPS);
#pragma unroll
        for (int t = 0; t < 16; t++) {
            int col = t * 8 + bq;
            float2 gg = *(float2*)&sB[896 + col];
            float2 bb = *(float2*)&sB[1024 + col];
            if (ok0) {
                float2 o;
                o.x = (y[t][0] - m0) * r0s * gg.x + bb.x;
                o.y = (y[t][1] - m0) * r0s * gg.y + bb.y;
                *(float2*)(out + gr0 * H + col) = o;
            }
            if (ok1) {
                float2 o;
                o.x = (y[t][2] - m1) * r1s * gg.x + bb.x;
                o.y = (y[t][3] - m1) * r1s * gg.y + bb.y;
                *(float2*)(out + gr1 * H + col) = o;
            }
        }
    }
#undef PREFETCH_N
#undef NCOMPUTE1
#undef NCOMPUTE2
}

// ===========================================================================
extern "C" void kernel_launch(void* const* d_in, const int* in_sizes, int n_in,
                              void* d_out, int out_size) {
    const float* h_V  = (const float*)d_in[0];
    const float* h_E  = (const float*)d_in[1];
    const void*  eidx = (const void*)d_in[2];
    const float* W1 = (const float*)d_in[3];
    const float* b1 = (const float*)d_in[4];
    const float* W2 = (const float*)d_in[5];
    const float* b2 = (const float*)d_in[6];
    const float* W3 = (const float*)d_in[7];
    const float* b3 = (const float*)d_in[8];
    const float* D1 = (const float*)d_in[9];
    const float* db1 = (const float*)d_in[10];
    const float* D2 = (const float*)d_in[11];
    const float* db2 = (const float*)d_in[12];
    const float* g1 = (const float*)d_in[13];
    const float* be1 = (const float*)d_in[14];
    const float* g2 = (const float*)d_in[15];
    const float* be2 = (const float*)d_in[16];
    float* out = (float*)d_out;

    cudaFuncSetAttribute(edge_mma_kernel, cudaFuncAttributeMaxDynamicSharedMemorySize, EDGE_SMEM);
    cudaFuncSetAttribute(node_mma_kernel, cudaFuncAttributeMaxDynamicSharedMemorySize, NODE_SMEM);

    void* dh_ptr = nullptr;
    cudaGetSymbolAddress(&dh_ptr, g_dh);
    cudaMemsetAsync(dh_ptr, 0, sizeof(float) * (size_t)N_NODES * H, 0);

    detect_idx_kernel<<<1, 1>>>(eidx);
    prep_weights_kernel<<<768, 256>>>(W1, W2, W3, D1, D2);
    edge_mma_kernel<<<N_EDGES / M_TILE, 256, EDGE_SMEM>>>(h_E, eidx, b1, b2, b3);
    node_mma_kernel<<<(N_NODES + 127) / 128, 256, NODE_SMEM>>>(
        h_V, db1, db2, g1, be1, g2, be2, out);
}

// round 7
// speedup vs baseline: 9.1337x; 1.8357x over previous
#include <cuda_runtime.h>
#include <cuda_bf16.h>
#include <cuda_fp16.h>
#include <cstdint>

#define N_NODES 100000
#define N_EDGES 800000
#define H 128
#define HE 256
#define EPS 1e-5f

// ---------------- shared geometry ----------------
#define M_TILE 128
#define SA_STRIDE 264       // padded elems per A row (528B ≡ 16 mod 128)
#define SB_STRIDE 136       // padded elems per B row (272B ≡ 16 mod 128)
#define ECHUNK 17408        // 64 rows * 136 * 2B (fp16)

// ---------------- edge kernel smem ----------------
#define OFF_AHI  1536
#define OFF_SB   (1536 + 67584)             // 69120
#define EDGE_SMEM (69120 + 2 * ECHUNK)      // 103936  -> 2 CTAs/SM

// ---------------- node kernel smem ----------------
#define OFF_A1HI  4608
#define OFF_A1LO  (4608 + 34816)
#define OFF_NB    (4608 + 69632)            // 74240
#define NODE_SMEM (OFF_NB + 2 * ECHUNK)     // 109056

// ---------------- globals ----------------
__device__ float g_dh[(size_t)N_NODES * H];
__device__ int g_idx_is64;
// edge weights: 8 chunks fp16
__device__ __align__(1024) unsigned char g_Bh16[8 * ECHUNK];
// node weights: 16 units fp16, stream order:
// for c in 0..3: D1[k0-63, n128c..], D1[k64-127,...], D2[k128c+0-63], D2[k128c+64-127]
__device__ __align__(1024) unsigned char g_Bn16[16 * ECHUNK];

// ===========================================================================
// PTX helpers (baseline ISA only)
// ===========================================================================
__device__ __forceinline__ uint32_t smem_u32(const void* p) {
    uint32_t a;
    asm("{ .reg .u64 t; cvta.to.shared.u64 t, %1; cvt.u32.u64 %0, t; }" : "=r"(a) : "l"(p));
    return a;
}
__device__ __forceinline__ void ldsm_x4(uint32_t* r, uint32_t addr) {
    asm volatile("ldmatrix.sync.aligned.m8n8.x4.shared.b16 {%0,%1,%2,%3}, [%4];"
                 : "=r"(r[0]), "=r"(r[1]), "=r"(r[2]), "=r"(r[3]) : "r"(addr));
}
__device__ __forceinline__ void ldsm_x4_t(uint32_t* r, uint32_t addr) {
    asm volatile("ldmatrix.sync.aligned.m8n8.x4.trans.shared.b16 {%0,%1,%2,%3}, [%4];"
                 : "=r"(r[0]), "=r"(r[1]), "=r"(r[2]), "=r"(r[3]) : "r"(addr));
}
__device__ __forceinline__ void mma16816h(float* d, const uint32_t* a, uint32_t b0, uint32_t b1) {
    asm volatile("mma.sync.aligned.m16n8k16.row.col.f32.f16.f16.f32 "
                 "{%0,%1,%2,%3}, {%4,%5,%6,%7}, {%8,%9}, {%0,%1,%2,%3};"
                 : "+f"(d[0]), "+f"(d[1]), "+f"(d[2]), "+f"(d[3])
                 : "r"(a[0]), "r"(a[1]), "r"(a[2]), "r"(a[3]), "r"(b0), "r"(b1));
}
__device__ __forceinline__ void cp_async16(uint32_t saddr, const void* g) {
    asm volatile("cp.async.cg.shared.global [%0], [%1], 16;" :: "r"(saddr), "l"(g));
}
#define CP_COMMIT() asm volatile("cp.async.commit_group;")
#define CP_WAIT0()  asm volatile("cp.async.wait_group 0;" ::: "memory")

// fp16 hi-only pack
__device__ __forceinline__ uint32_t pack_h(float v0, float v1) {
    return (uint32_t)__half_as_ushort(__float2half_rn(v0)) |
           ((uint32_t)__half_as_ushort(__float2half_rn(v1)) << 16);
}
// fp16 hi/lo split pack (22-bit effective)
__device__ __forceinline__ void split_pack_h(float v0, float v1, uint32_t& hi, uint32_t& lo) {
    __half h0 = __float2half_rn(v0), h1 = __float2half_rn(v1);
    hi = (uint32_t)__half_as_ushort(h0) | ((uint32_t)__half_as_ushort(h1) << 16);
    float r0 = v0 - __half2float(h0), r1 = v1 - __half2float(h1);
    lo = (uint32_t)__half_as_ushort(__float2half_rn(r0)) |
         ((uint32_t)__half_as_ushort(__float2half_rn(r1)) << 16);
}
__device__ __forceinline__ float2 unpack_h2sum(uint32_t hi, uint32_t lo) {
    float2 r;
    r.x = __half2float(__ushort_as_half((unsigned short)(hi & 0xffff))) +
          __half2float(__ushort_as_half((unsigned short)(lo & 0xffff)));
    r.y = __half2float(__ushort_as_half((unsigned short)(hi >> 16))) +
          __half2float(__ushort_as_half((unsigned short)(lo >> 16)));
    return r;
}

// single-term fp16 k16 step (edge): aH x bH, 16 mma
#define KSTEP_E1(ACC, fAh, sBhi, brow) do { \
    _Pragma("unroll") for (int p = 0; p < 8; p++) { \
        uint32_t bh[4]; \
        uint32_t _bo = b_frag_off + (brow) + (uint32_t)(p * 16) * 2; \
        ldsm_x4_t(bh, (sBhi) + _bo); \
        mma16816h((ACC)[2 * p],     fAh, bh[0], bh[1]); \
        mma16816h((ACC)[2 * p + 1], fAh, bh[2], bh[3]); \
    } } while (0)

// 2-term fp16 k16 step (node): (aH + aL) x bH, 32 mma
#define KSTEP_N2(ACC, fAh, fAl, sBhi, brow) do { \
    _Pragma("unroll") for (int p = 0; p < 8; p++) { \
        uint32_t bh[4]; \
        uint32_t _bo = b_frag_off + (brow) + (uint32_t)(p * 16) * 2; \
        ldsm_x4_t(bh, (sBhi) + _bo); \
        mma16816h((ACC)[2 * p],     fAh, bh[0], bh[1]); \
        mma16816h((ACC)[2 * p],     fAl, bh[0], bh[1]); \
        mma16816h((ACC)[2 * p + 1], fAh, bh[2], bh[3]); \
        mma16816h((ACC)[2 * p + 1], fAl, bh[2], bh[3]); \
    } } while (0)

// ---------------------------------------------------------------------------
__global__ void detect_idx_kernel(const void* eidx) {
    const long long* p = (const long long*)eidx;
    int is64 = 1;
    for (int i = 0; i < 64; i++) {
        long long v = p[i];
        if (v < 0 || v >= N_NODES) { is64 = 0; break; }
    }
    g_idx_is64 = is64;
}

// ---------------------------------------------------------------------------
// Weight prep: all weights -> fp16, padded [K][N] layout
// ---------------------------------------------------------------------------
__global__ void prep_weights_kernel(const float* __restrict__ W1,
                                    const float* __restrict__ W2,
                                    const float* __restrict__ W3,
                                    const float* __restrict__ D1,
                                    const float* __restrict__ D2) {
    int idx = blockIdx.x * 256 + threadIdx.x;    // 0 .. 196607
    if (idx < 65536) {
        int n = idx & 127;
        int krow = idx >> 7;
        const float* W; int k, unit;
        if (krow < 256)      { W = W1; k = krow;       unit = krow >> 6; }
        else if (krow < 384) { W = W2; k = krow - 256; unit = 4 + ((krow - 256) >> 6); }
        else                 { W = W3; k = krow - 384; unit = 6 + ((krow - 384) >> 6); }
        float v = W[(size_t)k * 128 + n];
        int kk = k & 63;
        *(unsigned short*)(g_Bh16 + (size_t)unit * ECHUNK + (size_t)(kk * SB_STRIDE + n) * 2) =
            __half_as_ushort(__float2half_rn(v));
        return;
    }
    float v; int unit, kk, n;
    if (idx < 131072) {
        int i = idx - 65536;                     // D1: 128 x 512
        int k = i >> 9, n512 = i & 511;
        int c = n512 >> 7; n = n512 & 127;
        int half = k >> 6; kk = k & 63;
        unit = 4 * c + half;
        v = D1[(size_t)k * 512 + n512];
    } else {
        int i = idx - 131072;                    // D2: 512 x 128
        int k = i >> 7; n = i & 127;
        int c = k >> 7, krem = k & 127;
        int half = krem >> 6; kk = krem & 63;
        unit = 4 * c + 2 + half;
        v = D2[(size_t)k * 128 + n];
    }
    *(unsigned short*)(g_Bn16 + (size_t)unit * ECHUNK + (size_t)(kk * SB_STRIDE + n) * 2) =
        __half_as_ushort(__float2half_rn(v));
}

// ===========================================================================
// Edge kernel: single-term fp16 HMMA 3-layer MLP + scatter (2 CTAs/SM)
// ===========================================================================
__global__ __launch_bounds__(256, 2)
void edge_mma_kernel(const float* __restrict__ hE, const void* __restrict__ eidx,
                     const float* __restrict__ b1, const float* __restrict__ b2,
                     const float* __restrict__ b3) {
    extern __shared__ char sm[];
    const uint32_t sb = smem_u32(sm);
    const int tid = threadIdx.x, wid = tid >> 5, lane = tid & 31;
    const long long ebase = (long long)blockIdx.x * M_TILE;

    if (tid < 128) {
        ((float*)sm)[tid] = b1[tid];
        ((float*)sm)[128 + tid] = b2[tid];
        ((float*)sm)[256 + tid] = b3[tid];
    }

    for (int i = tid; i < 1088; i += 256)
        cp_async16(sb + OFF_SB + i * 16, g_Bh16 + i * 16);
    CP_COMMIT();

    // stage layer-1 A: h_E [128 x 256] f32 -> fp16, padded stride
    {
        const float4* gE = (const float4*)(hE + ebase * HE);
        char* aHi = sm + OFF_AHI;
        for (int i = tid; i < 128 * 64; i += 256) {
            int row = i >> 6, c4 = i & 63;
            float4 v = gE[i];
            uint32_t off = (uint32_t)(row * SA_STRIDE + c4 * 4) * 2;
            *(uint2*)(aHi + off) = make_uint2(pack_h(v.x, v.y), pack_h(v.z, v.w));
        }
    }
    CP_WAIT0();
    __syncthreads();

    const int mrow = lane & 7, mid = lane >> 3;
    const uint32_t a_row_off =
        (uint32_t)((wid * 16 + (mid & 1) * 8 + mrow) * SA_STRIDE + (mid >> 1) * 8) * 2;
    const uint32_t b_frag_off =
        (uint32_t)(((mid & 1) * 8 + mrow) * SB_STRIDE + (mid >> 1) * 8) * 2;
    const int bq = 2 * (lane & 3);

    float acc[16][4];
    uint32_t aH[8][4];
    float* sBias = (float*)sm;

#define ZERO_ACC() do { \
    _Pragma("unroll") for (int t = 0; t < 16; t++) \
        { acc[t][0] = 0.f; acc[t][1] = 0.f; acc[t][2] = 0.f; acc[t][3] = 0.f; } } while (0)

#define PREFETCH(c) do { \
    const unsigned char* _src = g_Bh16 + (c) * ECHUNK; \
    uint32_t _dst = sb + OFF_SB + ((c) & 1) * ECHUNK; \
    for (int i = tid; i < 1088; i += 256) cp_async16(_dst + i * 16, _src + i * 16); \
    CP_COMMIT(); } while (0)

#define COMPUTE_SMEM(c) do { \
    uint32_t _sBhi = sb + OFF_SB + ((c) & 1) * ECHUNK; \
    _Pragma("unroll") for (int js = 0; js < 4; js++) { \
        uint32_t fAh[4]; \
        uint32_t _acol = (uint32_t)((c) * 64 + js * 16) * 2; \
        ldsm_x4(fAh, sb + OFF_AHI + a_row_off + _acol); \
        KSTEP_E1(acc, fAh, _sBhi, (uint32_t)(js * 16 * SB_STRIDE) * 2); \
    } } while (0)

#define COMPUTE_REG(JB, c) do { \
    uint32_t _sBhi = sb + OFF_SB + ((c) & 1) * ECHUNK; \
    _Pragma("unroll") for (int js = 0; js < 4; js++) { \
        KSTEP_E1(acc, aH[(JB) + js], _sBhi, (uint32_t)(js * 16 * SB_STRIDE) * 2); \
    } } while (0)

#define EPILOGUE_RELU(biasBase) do { \
    _Pragma("unroll") for (int t = 0; t < 16; t++) { \
        float2 bb = *(float2*)&sBias[(biasBase) + t * 8 + bq]; \
        float v0 = fmaxf(acc[t][0] + bb.x, 0.f); \
        float v1 = fmaxf(acc[t][1] + bb.y, 0.f); \
        float v2 = fmaxf(acc[t][2] + bb.x, 0.f); \
        float v3 = fmaxf(acc[t][3] + bb.y, 0.f); \
        int _j = t >> 1, _b = (t & 1) * 2; \
        aH[_j][_b] = pack_h(v0, v1); aH[_j][_b + 1] = pack_h(v2, v3); \
    } } while (0)

    ZERO_ACC();
    PREFETCH(1); COMPUTE_SMEM(0); CP_WAIT0(); __syncthreads();
    PREFETCH(2); COMPUTE_SMEM(1); CP_WAIT0(); __syncthreads();
    PREFETCH(3); COMPUTE_SMEM(2); CP_WAIT0(); __syncthreads();
    PREFETCH(4); COMPUTE_SMEM(3); CP_WAIT0(); __syncthreads();
    EPILOGUE_RELU(0); ZERO_ACC();
    PREFETCH(5); COMPUTE_REG(0, 4); CP_WAIT0(); __syncthreads();
    PREFETCH(6); COMPUTE_REG(4, 5); CP_WAIT0(); __syncthreads();
    EPILOGUE_RELU(128); ZERO_ACC();
    PREFETCH(7); COMPUTE_REG(0, 6); CP_WAIT0(); __syncthreads();
    COMPUTE_REG(4, 7); __syncthreads();

    // layer-3 epilogue: bias -> padded smem (reuse A region) -> coalesced scatter
    {
        float* sOut = (float*)(sm + OFF_AHI);   // 128 x 132 f32 = 67584 B
        int row0 = wid * 16 + (lane >> 2);
#pragma unroll
        for (int t = 0; t < 16; t++) {
            float2 bb = *(float2*)&sBias[256 + t * 8 + bq];
            *(float2*)&sOut[row0 * 132 + t * 8 + bq] =
                make_float2(acc[t][0] + bb.x, acc[t][1] + bb.y);
            *(float2*)&sOut[(row0 + 8) * 132 + t * 8 + bq] =
                make_float2(acc[t][2] + bb.x, acc[t][3] + bb.y);
        }
        __syncthreads();

        const int is64 = g_idx_is64;
        for (int e = wid; e < 128; e += 8) {
            long long s = is64 ? ((const long long*)eidx)[ebase + e]
                               : (long long)((const int*)eidx)[ebase + e];
            float* dst = g_dh + (size_t)s * H;
            const float* srow = sOut + e * 132;
#pragma unroll
            for (int q = 0; q < 4; q++) {
                int col = lane + q * 32;
                atomicAdd(dst + col, srow[col]);
            }
        }
    }
#undef ZERO_ACC
#undef PREFETCH
#undef COMPUTE_SMEM
#undef COMPUTE_REG
#undef EPILOGUE_RELU
}

// ===========================================================================
// Node kernel: 2-term fp16-weight HMMA FFN, LN in fragment registers
// ===========================================================================
__global__ __launch_bounds__(256, 1)
void node_mma_kernel(const float* __restrict__ hV,
                     const float* __restrict__ db1, const float* __restrict__ db2,
                     const float* __restrict__ g1, const float* __restrict__ be1,
                     const float* __restrict__ g2, const float* __restrict__ be2,
                     float* __restrict__ out) {
    extern __shared__ char sm[];
    const uint32_t sb = smem_u32(sm);
    const int tid = threadIdx.x, wid = tid >> 5, lane = tid & 31;
    const long long nbase = (long long)blockIdx.x * 128;

    float* sB = (float*)sm;
    for (int i = tid; i < 512; i += 256) sB[i] = db1[i];
    if (tid < 128) {
        sB[512 + tid] = db2[tid];
        sB[640 + tid] = g1[tid];  sB[768 + tid] = be1[tid];
        sB[896 + tid] = g2[tid];  sB[1024 + tid] = be2[tid];
    }

#define PREFETCH_N(s) do { \
    const unsigned char* _src = g_Bn16 + (s) * ECHUNK; \
    uint32_t _dst = sb + OFF_NB + ((s) & 1) * ECHUNK; \
    for (int i = tid; i < 1088; i += 256) cp_async16(_dst + i * 16, _src + i * 16); \
    CP_COMMIT(); } while (0)

    PREFETCH_N(0);

    const int mrow = lane & 7, mid = lane >> 3;
    const uint32_t a_row_off =
        (uint32_t)((wid * 16 + (mid & 1) * 8 + mrow) * SB_STRIDE + (mid >> 1) * 8) * 2;
    const uint32_t b_frag_off =
        (uint32_t)(((mid & 1) * 8 + mrow) * SB_STRIDE + (mid >> 1) * 8) * 2;
    const int bq = 2 * (lane & 3);
    const int r0 = wid * 16 + (lane >> 2);
    const long long gr0 = nbase + r0, gr1 = gr0 + 8;
    const bool ok0 = gr0 < N_NODES, ok1 = gr1 < N_NODES;

    // ---- x = hV + dh/30 in fragment layout; LN1 in registers; A1 = fp16 hi/lo ----
    {
        float x[16][4];
#pragma unroll
        for (int t = 0; t < 16; t++) {
            int col = t * 8 + bq;
            if (ok0) {
                float2 v = *(const float2*)(hV + gr0 * H + col);
                float2 d = *(const float2*)(g_dh + gr0 * H + col);
                x[t][0] = v.x + d.x * (1.f / 30.f);
                x[t][1] = v.y + d.y * (1.f / 30.f);
            } else { x[t][0] = 0.f; x[t][1] = 0.f; }
            if (ok1) {
                float2 v = *(const float2*)(hV + gr1 * H + col);
                float2 d = *(const float2*)(g_dh + gr1 * H + col);
                x[t][2] = v.x + d.x * (1.f / 30.f);
                x[t][3] = v.y + d.y * (1.f / 30.f);
            } else { x[t][2] = 0.f; x[t][3] = 0.f; }
        }
        float s0 = 0.f, s1 = 0.f;
#pragma unroll
        for (int t = 0; t < 16; t++) { s0 += x[t][0] + x[t][1]; s1 += x[t][2] + x[t][3]; }
        s0 += __shfl_xor_sync(~0u, s0, 1); s0 += __shfl_xor_sync(~0u, s0, 2);
        s1 += __shfl_xor_sync(~0u, s1, 1); s1 += __shfl_xor_sync(~0u, s1, 2);
        float m0 = s0 * (1.f / H), m1 = s1 * (1.f / H);
        float q0 = 0.f, q1 = 0.f;
#pragma unroll
        for (int t = 0; t < 16; t++) {
            float d0 = x[t][0] - m0, d1 = x[t][1] - m0;
            float d2 = x[t][2] - m1, d3 = x[t][3] - m1;
            q0 += d0 * d0 + d1 * d1; q1 += d2 * d2 + d3 * d3;
        }
        q0 += __shfl_xor_sync(~0u, q0, 1); q0 += __shfl_xor_sync(~0u, q0, 2);
        q1 += __shfl_xor_sync(~0u, q1, 1); q1 += __shfl_xor_sync(~0u, q1, 2);
        float r0s = rsqrtf(q0 * (1.f / H) + EPS), r1s = rsqrtf(q1 * (1.f / H) + EPS);
#pragma unroll
        for (int t = 0; t < 16; t++) {
            int col = t * 8 + bq;
            float2 gg = *(float2*)&sB[640 + col];
            float2 bb = *(float2*)&sB[768 + col];
            float h0 = (x[t][0] - m0) * r0s * gg.x + bb.x;
            float h1 = (x[t][1] - m0) * r0s * gg.y + bb.y;
            float h2 = (x[t][2] - m1) * r1s * gg.x + bb.x;
            float h3 = (x[t][3] - m1) * r1s * gg.y + bb.y;
            uint32_t hi0, lo0, hi1, lo1;
            split_pack_h(h0, h1, hi0, lo0);
            split_pack_h(h2, h3, hi1, lo1);
            uint32_t o0 = (uint32_t)(r0 * SB_STRIDE + col) * 2;
            uint32_t o1 = (uint32_t)((r0 + 8) * SB_STRIDE + col) * 2;
            *(uint32_t*)(sm + OFF_A1HI + o0) = hi0;
            *(uint32_t*)(sm + OFF_A1LO + o0) = lo0;
            *(uint32_t*)(sm + OFF_A1HI + o1) = hi1;
            *(uint32_t*)(sm + OFF_A1LO + o1) = lo1;
        }
    }
    CP_WAIT0();
    __syncthreads();

    float acc2[16][4];
#pragma unroll
    for (int t = 0; t < 16; t++)
        { acc2[t][0] = 0.f; acc2[t][1] = 0.f; acc2[t][2] = 0.f; acc2[t][3] = 0.f; }

    uint32_t aH[8][4], aL[8][4];

#define NCOMPUTE1(half, s) do { \
    uint32_t _sBhi = sb + OFF_NB + ((s) & 1) * ECHUNK; \
    _Pragma("unroll") for (int js = 0; js < 4; js++) { \
        uint32_t fAh[4], fAl[4]; \
        uint32_t _acol = (uint32_t)((half) * 64 + js * 16) * 2; \
        ldsm_x4(fAh, sb + OFF_A1HI + a_row_off + _acol); \
        ldsm_x4(fAl, sb + OFF_A1LO + a_row_off + _acol); \
        KSTEP_N2(acc1, fAh, fAl, _sBhi, (uint32_t)(js * 16 * SB_STRIDE) * 2); \
    } } while (0)

#define NCOMPUTE2(JB, s) do { \
    uint32_t _sBhi = sb + OFF_NB + ((s) & 1) * ECHUNK; \
    _Pragma("unroll") for (int js = 0; js < 4; js++) { \
        KSTEP_N2(acc2, aH[(JB) + js], aL[(JB) + js], _sBhi, (uint32_t)(js * 16 * SB_STRIDE) * 2); \
    } } while (0)

#pragma unroll 1
    for (int c = 0; c < 4; c++) {
        const int s0u = 4 * c;
        float acc1[16][4];
#pragma unroll
        for (int t = 0; t < 16; t++)
            { acc1[t][0] = 0.f; acc1[t][1] = 0.f; acc1[t][2] = 0.f; acc1[t][3] = 0.f; }

        PREFETCH_N(s0u + 1); NCOMPUTE1(0, s0u);     CP_WAIT0(); __syncthreads();
        PREFETCH_N(s0u + 2); NCOMPUTE1(1, s0u + 1); CP_WAIT0(); __syncthreads();

        // bias + relu + repack -> GEMM2 A fragments (fp16 hi/lo)
#pragma unroll
        for (int t = 0; t < 16; t++) {
            float2 bb = *(float2*)&sB[c * 128 + t * 8 + bq];
            float v0 = fmaxf(acc1[t][0] + bb.x, 0.f);
            float v1 = fmaxf(acc1[t][1] + bb.y, 0.f);
            float v2 = fmaxf(acc1[t][2] + bb.x, 0.f);
            float v3 = fmaxf(acc1[t][3] + bb.y, 0.f);
            uint32_t h01, l01, h23, l23;
            split_pack_h(v0, v1, h01, l01);
            split_pack_h(v2, v3, h23, l23);
            int _j = t >> 1, _b = (t & 1) * 2;
            aH[_j][_b] = h01; aH[_j][_b + 1] = h23;
            aL[_j][_b] = l01; aL[_j][_b + 1] = l23;
        }

        PREFETCH_N(s0u + 3); NCOMPUTE2(0, s0u + 2); CP_WAIT0(); __syncthreads();
        if (c < 3) {
            PREFETCH_N(s0u + 4); NCOMPUTE2(4, s0u + 3); CP_WAIT0(); __syncthreads();
        } else {
            NCOMPUTE2(4, s0u + 3); __syncthreads();
        }
    }

    // ---- residual + LN2 + store ----
    {
        float y[16][4];
#pragma unroll
        for (int t = 0; t < 16; t++) {
            int col = t * 8 + bq;
            float2 d2 = *(float2*)&sB[512 + col];
            uint32_t o0 = (uint32_t)(r0 * SB_STRIDE + col) * 2;
            uint32_t o1 = (uint32_t)((r0 + 8) * SB_STRIDE + col) * 2;
            float2 h01 = unpack_h2sum(*(uint32_t*)(sm + OFF_A1HI + o0),
                                      *(uint32_t*)(sm + OFF_A1LO + o0));
            float2 h23 = unpack_h2sum(*(uint32_t*)(sm + OFF_A1HI + o1),
                                      *(uint32_t*)(sm + OFF_A1LO + o1));
            y[t][0] = h01.x + acc2[t][0] + d2.x;
            y[t][1] = h01.y + acc2[t][1] + d2.y;
            y[t][2] = h23.x + acc2[t][2] + d2.x;
            y[t][3] = h23.y + acc2[t][3] + d2.y;
        }
        float s0 = 0.f, s1 = 0.f;
#pragma unroll
        for (int t = 0; t < 16; t++) { s0 += y[t][0] + y[t][1]; s1 += y[t][2] + y[t][3]; }
        s0 += __shfl_xor_sync(~0u, s0, 1); s0 += __shfl_xor_sync(~0u, s0, 2);
        s1 += __shfl_xor_sync(~0u, s1, 1); s1 += __shfl_xor_sync(~0u, s1, 2);
        float m0 = s0 * (1.f / H), m1 = s1 * (1.f / H);
        float q0 = 0.f, q1 = 0.f;
#pragma unroll
        for (int t = 0; t < 16; t++) {
            float d0 = y[t][0] - m0, d1 = y[t][1] - m0;
            float d2 = y[t][2] - m1, d3 = y[t][3] - m1;
            q0 += d0 * d0 + d1 * d1; q1 += d2 * d2 + d3 * d3;
        }
        q0 += __shfl_xor_sync(~0u, q0, 1); q0 += __shfl_xor_sync(~0u, q0, 2);
        q1 += __shfl_xor_sync(~0u, q1, 1); q1 += __shfl_xor_sync(~0u, q1, 2);
        float r0s = rsqrtf(q0 * (1.f / H) + EPS), r1s = rsqrtf(q1 * (1.f / H) + EPS);
#pragma unroll
        for (int t = 0; t < 16; t++) {
            int col = t * 8 + bq;
            float2 gg = *(float2*)&sB[896 + col];
            float2 bb = *(float2*)&sB[1024 + col];
            if (ok0) {
                float2 o;
                o.x = (y[t][0] - m0) * r0s * gg.x + bb.x;
                o.y = (y[t][1] - m0) * r0s * gg.y + bb.y;
                *(float2*)(out + gr0 * H + col) = o;
            }
            if (ok1) {
                float2 o;
                o.x = (y[t][2] - m1) * r1s * gg.x + bb.x;
                o.y = (y[t][3] - m1) * r1s * gg.y + bb.y;
                *(float2*)(out + gr1 * H + col) = o;
            }
        }
    }
#undef PREFETCH_N
#undef NCOMPUTE1
#undef NCOMPUTE2
}

// ===========================================================================
extern "C" void kernel_launch(void* const* d_in, const int* in_sizes, int n_in,
                              void* d_out, int out_size) {
    const float* h_V  = (const float*)d_in[0];
    const float* h_E  = (const float*)d_in[1];
    const void*  eidx = (const void*)d_in[2];
    const float* W1 = (const float*)d_in[3];
    const float* b1 = (const float*)d_in[4];
    const float* W2 = (const float*)d_in[5];
    const float* b2 = (const float*)d_in[6];
    const float* W3 = (const float*)d_in[7];
    const float* b3 = (const float*)d_in[8];
    const float* D1 = (const float*)d_in[9];
    const float* db1 = (const float*)d_in[10];
    const float* D2 = (const float*)d_in[11];
    const float* db2 = (const float*)d_in[12];
    const float* g1 = (const float*)d_in[13];
    const float* be1 = (const float*)d_in[14];
    const float* g2 = (const float*)d_in[15];
    const float* be2 = (const float*)d_in[16];
    float* out = (float*)d_out;

    cudaFuncSetAttribute(edge_mma_kernel, cudaFuncAttributeMaxDynamicSharedMemorySize, EDGE_SMEM);
    cudaFuncSetAttribute(node_mma_kernel, cudaFuncAttributeMaxDynamicSharedMemorySize, NODE_SMEM);

    void* dh_ptr = nullptr;
    cudaGetSymbolAddress(&dh_ptr, g_dh);
    cudaMemsetAsync(dh_ptr, 0, sizeof(float) * (size_t)N_NODES * H, 0);

    detect_idx_kernel<<<1, 1>>>(eidx);
    prep_weights_kernel<<<768, 256>>>(W1, W2, W3, D1, D2);
    edge_mma_kernel<<<N_EDGES / M_TILE, 256, EDGE_SMEM>>>(h_E, eidx, b1, b2, b3);
    node_mma_kernel<<<(N_NODES + 127) / 128, 256, NODE_SMEM>>>(
        h_V, db1, db2, g1, be1, g2, be2, out);
}